// round 5
// baseline (speedup 1.0000x reference)
#include <cuda_runtime.h>
#include <stdint.h>
#include <math.h>

#define E_ 16
#define H_ 2048
#define I_ 768
#define TWOI 1536
#define T_ 4096
#define K2DIM 12288
#define KC 32

#define ROW_STRIDE 160
#define A_STAGE (128 * ROW_STRIDE)   // 20480
#define B_STAGE (128 * ROW_STRIDE)   // 20480
#define SMEM_BYTES (2 * A_STAGE + 2 * B_STAGE)  // 81920

__device__ float g_inter[(size_t)T_ * K2DIM];

static __device__ __forceinline__ uint32_t f2tf(float x) {
    uint32_t u; asm("cvt.rna.tf32.f32 %0, %1;" : "=r"(u) : "f"(x)); return u;
}
static __device__ __forceinline__ void ldsm4(uint32_t r[4], uint32_t a) {
    asm volatile("ldmatrix.sync.aligned.m8n8.x4.shared.b16 {%0,%1,%2,%3}, [%4];"
                 : "=r"(r[0]), "=r"(r[1]), "=r"(r[2]), "=r"(r[3]) : "r"(a));
}
static __device__ __forceinline__ void sts128(uint32_t a, uint32_t x, uint32_t y, uint32_t z, uint32_t w) {
    asm volatile("st.shared.v4.b32 [%0], {%1,%2,%3,%4};" :: "r"(a), "r"(x), "r"(y), "r"(z), "r"(w) : "memory");
}
static __device__ __forceinline__ void cp16(uint32_t d, const void* s) {
    asm volatile("cp.async.ca.shared.global [%0], [%1], 16;" :: "r"(d), "l"(s) : "memory");
}
static __device__ __forceinline__ void mma_tf32(float c[4], const uint32_t a[4], uint32_t b0, uint32_t b1) {
    asm volatile("mma.sync.aligned.m16n8k8.row.col.f32.tf32.tf32.f32 "
                 "{%0,%1,%2,%3}, {%4,%5,%6,%7}, {%8,%9}, {%0,%1,%2,%3};"
                 : "+f"(c[0]), "+f"(c[1]), "+f"(c[2]), "+f"(c[3])
                 : "r"(a[0]), "r"(a[1]), "r"(a[2]), "r"(a[3]), "r"(b0), "r"(b1));
}
// smem address: row r, 16B-quad qd, with per-row XOR swizzle (conflict-free for
// cp.async writes, STS.128 transpose writes, and ldmatrix reads; banks
// (2r + qd^r) mod 8 form a permutation for any fixed qd or fixed r).
static __device__ __forceinline__ uint32_t smad(uint32_t base, int r, int qd) {
    return base + (uint32_t)r * ROW_STRIDE + (uint32_t)((qd ^ (r & 7)) << 4);
}

// MODE 1: inter[t, e*768+j] = rw*up*silu(gate). CTA: 128 t-rows x 64 j-cols
//   (gate+up interleaved: B rows 16i..16i+7 = gate 8-block i, +8 = up).
// MODE 2: out = inter @ DN_flat. CTA: 128 t-rows x 128 h-cols.
template<int MODE>
__global__ void __launch_bounds__(256, 2)
moe_mma(const float* __restrict__ Ain, const float* __restrict__ Bin,
        const float* __restrict__ SC, const float* __restrict__ RW,
        float* __restrict__ OUT)
{
    extern __shared__ char smraw[];
    const uint32_t sb = (uint32_t)__cvta_generic_to_shared(smraw);
    const uint32_t sA = sb, sB = sb + 2 * A_STAGE;

    const int tid = threadIdx.x, lane = tid & 31, wid = tid >> 5;
    const int warp_m = wid & 1, warp_n = wid >> 1;
    const int m0 = blockIdx.x * 128;

    int e = 0, j0 = 0, n0 = 0, lda, ldb, NC;
    const float* Ap;
    if (MODE == 1) { e = blockIdx.y / 12; j0 = (blockIdx.y % 12) * 64; Ap = Ain; lda = H_; ldb = TWOI; NC = H_ / KC; }
    else           { n0 = blockIdx.y * 128; Ap = g_inter; lda = K2DIM; ldb = H_; NC = K2DIM / KC; }

    // ---- B producer: slot = (n-quad nq 0..31) x (k-quad kq 0..7)
    const int kq = tid & 7, nq = tid >> 3;
    int h = 0, jl0 = 0;
    const float* bsrc;
    if (MODE == 1) {
        h = nq >> 4;                       // 0 = gate, 1 = up
        jl0 = 4 * (nq & 15);
        bsrc = Bin + (size_t)e * H_ * TWOI + (h ? (I_ + j0 + jl0) : (j0 + jl0));
    } else {
        bsrc = Bin + n0 + 4 * nq;
    }
    // ---- A producer (cp.async): row = tid>>1, 4 quads per thread
    const int arow = tid >> 1, aq0 = (tid & 1) * 4;

    // ---- ldmatrix lane constants
    const int mat = lane >> 3, q = lane & 7;
    const int aR = warp_m * 64 + (mat & 1) * 8 + q, aSeg = mat >> 1;
    const int bR = warp_n * 32 + (mat >> 1) * 8 + q, bSeg = mat & 1;

    float acc[4][4][4];
#pragma unroll
    for (int a = 0; a < 4; a++)
#pragma unroll
        for (int b = 0; b < 4; b++)
#pragma unroll
            for (int c = 0; c < 4; c++) acc[a][b][c] = 0.f;

    float4 bst[4];
    float scl;

    auto LDGB = [&](int c) {
        const int k0 = c * KC;
#pragma unroll
        for (int kk = 0; kk < 4; kk++)
            bst[kk] = *reinterpret_cast<const float4*>(bsrc + (size_t)(k0 + 4 * kq + kk) * ldb);
        if (MODE == 1) {
            scl = SC[e * 192 + (k0 >> 7) * 12 + h * 6 + (j0 >> 7)];
        } else {
            int ee = k0 / I_, band = (k0 - ee * I_) >> 7;
            scl = SC[(ee * 6 + band) * 16 + (n0 >> 7)];
        }
    };
    auto CPA = [&](int c, int buf) {
        const uint32_t ab = sA + buf * A_STAGE;
        const float* src = Ap + (size_t)(m0 + arow) * lda + c * KC;
#pragma unroll
        for (int i = 0; i < 4; i++)
            cp16(smad(ab, arow, aq0 + i), src + (aq0 + i) * 4);
        asm volatile("cp.async.commit_group;" ::: "memory");
    };
    auto STSB = [&](int buf) {
        const uint32_t bb = sB + buf * B_STAGE;
        const float* p = (const float*)bst;
#pragma unroll
        for (int jj = 0; jj < 4; jj++) {
            int r;
            if (MODE == 1) { int jl = jl0 + jj; r = ((jl >> 3) << 4) + (jl & 7) + (h << 3); }
            else           { r = 4 * nq + jj; }
            sts128(smad(bb, r, kq),
                   f2tf(p[0 * 4 + jj] * scl), f2tf(p[1 * 4 + jj] * scl),
                   f2tf(p[2 * 4 + jj] * scl), f2tf(p[3 * 4 + jj] * scl));
        }
    };
    auto COMPUTE = [&](int buf) {
        const uint32_t ab = sA + buf * A_STAGE, bb = sB + buf * B_STAGE;
#pragma unroll
        for (int s = 0; s < 4; s++) {
            uint32_t bf[2][4];
#pragma unroll
            for (int np = 0; np < 2; np++)
                ldsm4(bf[np], smad(bb, bR + np * 16, 2 * s + bSeg));
#pragma unroll
            for (int mi = 0; mi < 4; mi++) {
                uint32_t af[4];
                ldsm4(af, smad(ab, aR + mi * 16, 2 * s + aSeg));
#pragma unroll
                for (int i = 0; i < 4; i++) af[i] = f2tf(__uint_as_float(af[i]));
#pragma unroll
                for (int nt = 0; nt < 4; nt++)
                    mma_tf32(acc[mi][nt], af, bf[nt >> 1][(nt & 1) * 2], bf[nt >> 1][(nt & 1) * 2 + 1]);
            }
        }
    };

    // prologue
    CPA(0, 0); LDGB(0); STSB(0);
    asm volatile("cp.async.wait_group 0;" ::: "memory");
    __syncthreads();

#pragma unroll 1
    for (int c = 0; c < NC; c++) {
        const int buf = c & 1;
        const bool more = (c + 1 < NC);
        if (more) { CPA(c + 1, buf ^ 1); LDGB(c + 1); }
        COMPUTE(buf);
        if (more) STSB(buf ^ 1);
        asm volatile("cp.async.wait_group 0;" ::: "memory");
        __syncthreads();
    }

    // ---- epilogue
    const int g = lane >> 2, tg = lane & 3;
    if (MODE == 1) {
#pragma unroll
        for (int mi = 0; mi < 4; mi++) {
            const int r0 = m0 + warp_m * 64 + mi * 16 + g, r1 = r0 + 8;
            const float rw0 = RW[r0 * E_ + e], rw1 = RW[r1 * E_ + e];
#pragma unroll
            for (int np = 0; np < 2; np++) {
                const size_t col = (size_t)e * I_ + j0 + (2 * warp_n + np) * 8 + tg * 2;
                const float* gv = acc[mi][np * 2];
                const float* uv = acc[mi][np * 2 + 1];
                float2 v;
                v.x = rw0 * uv[0] * gv[0] / (1.f + __expf(-gv[0]));
                v.y = rw0 * uv[1] * gv[1] / (1.f + __expf(-gv[1]));
                *reinterpret_cast<float2*>(g_inter + (size_t)r0 * K2DIM + col) = v;
                v.x = rw1 * uv[2] * gv[2] / (1.f + __expf(-gv[2]));
                v.y = rw1 * uv[3] * gv[3] / (1.f + __expf(-gv[3]));
                *reinterpret_cast<float2*>(g_inter + (size_t)r1 * K2DIM + col) = v;
            }
        }
    } else {
#pragma unroll
        for (int mi = 0; mi < 4; mi++) {
            const int r0 = m0 + warp_m * 64 + mi * 16 + g, r1 = r0 + 8;
#pragma unroll
            for (int nt = 0; nt < 4; nt++) {
                const size_t col = (size_t)n0 + warp_n * 32 + nt * 8 + tg * 2;
                float2 v;
                v.x = acc[mi][nt][0]; v.y = acc[mi][nt][1];
                *reinterpret_cast<float2*>(OUT + (size_t)r0 * H_ + col) = v;
                v.x = acc[mi][nt][2]; v.y = acc[mi][nt][3];
                *reinterpret_cast<float2*>(OUT + (size_t)r1 * H_ + col) = v;
            }
        }
    }
}

extern "C" void kernel_launch(void* const* d_in, const int* in_sizes, int n_in,
                              void* d_out, int out_size) {
    (void)in_sizes; (void)n_in; (void)out_size;
    const float* X   = (const float*)d_in[0];  // hidden_states [T,H]
    const float* RW  = (const float*)d_in[1];  // routing_weights [T,E]
    const float* GU  = (const float*)d_in[2];  // gate_up_proj [E,H,2I]
    const float* GUS = (const float*)d_in[3];  // [E,16,12]
    const float* DN  = (const float*)d_in[4];  // down_proj [E,I,H]
    const float* DNS = (const float*)d_in[5];  // [E,6,16]
    float* OUT = (float*)d_out;

    cudaFuncSetAttribute(moe_mma<1>, cudaFuncAttributeMaxDynamicSharedMemorySize, SMEM_BYTES);
    cudaFuncSetAttribute(moe_mma<2>, cudaFuncAttributeMaxDynamicSharedMemorySize, SMEM_BYTES);

    // grid.x = m-tiles fastest: concurrent CTAs share the same weight tiles (L2 reuse)
    moe_mma<1><<<dim3(32, 192), 256, SMEM_BYTES>>>(X, GU, GUS, RW, nullptr);
    moe_mma<2><<<dim3(32, 16), 256, SMEM_BYTES>>>(nullptr, DN, DNS, nullptr, OUT);
}

// round 6
// speedup vs baseline: 1.2031x; 1.2031x over previous
#include <cuda_runtime.h>
#include <stdint.h>
#include <math.h>

#define E_ 16
#define H_ 2048
#define I_ 768
#define TWOI 1536
#define T_ 4096
#define K2DIM 12288
#define KC 32
#define STAGES 3

#define A_STAGE (128*128)
#define B_STAGE (256*128)
#define SMEM_BYTES (STAGES*(A_STAGE+B_STAGE))   // 147456

__device__ float g_inter[(size_t)T_ * K2DIM];   // [T][E*I]  (tf32 values)
__device__ float g_gut [(size_t)E_ * TWOI * H_]; // [e][j'][h] scaled tf32 (j'<768 gate, >=768 up)
__device__ float g_dnt [(size_t)H_ * K2DIM];     // [h][e*I+i] scaled tf32
__device__ float g_xt  [(size_t)T_ * H_];        // tf32(X)

static __device__ __forceinline__ uint32_t f2tf(float x) {
    uint32_t u; asm("cvt.rna.tf32.f32 %0, %1;" : "=r"(u) : "f"(x)); return u;
}
static __device__ __forceinline__ void ldsm4(uint32_t r[4], uint32_t a) {
    asm volatile("ldmatrix.sync.aligned.m8n8.x4.shared.b16 {%0,%1,%2,%3}, [%4];"
                 : "=r"(r[0]), "=r"(r[1]), "=r"(r[2]), "=r"(r[3]) : "r"(a));
}
static __device__ __forceinline__ void cp16(uint32_t d, const void* s) {
    asm volatile("cp.async.ca.shared.global [%0], [%1], 16;" :: "r"(d), "l"(s) : "memory");
}
static __device__ __forceinline__ void mma_tf32(float c[4], const uint32_t a[4], uint32_t b0, uint32_t b1) {
    asm volatile("mma.sync.aligned.m16n8k8.row.col.f32.tf32.tf32.f32 "
                 "{%0,%1,%2,%3}, {%4,%5,%6,%7}, {%8,%9}, {%0,%1,%2,%3};"
                 : "+f"(c[0]), "+f"(c[1]), "+f"(c[2]), "+f"(c[3])
                 : "r"(a[0]), "r"(a[1]), "r"(a[2]), "r"(a[3]), "r"(b0), "r"(b1));
}
// row r, 16B quad qd; XOR swizzle -> conflict-free for cp.async writes + ldmatrix
static __device__ __forceinline__ uint32_t smad(uint32_t base, int r, int qd) {
    return base + (uint32_t)r * 128u + (uint32_t)((qd ^ (r & 7)) << 4);
}

// ---------------- preprocessing kernels ----------------
__global__ void tr_gu(const float* __restrict__ GU, const float* __restrict__ GUS,
                      float* __restrict__ O) {
    __shared__ float t[32][33];
    const int tx = threadIdx.x, ty = threadIdx.y;
    const int c0 = blockIdx.x * 32, r0 = blockIdx.y * 32, e = blockIdx.z;
    const float* src = GU + ((size_t)e * H_ + r0) * TWOI + c0;
    const float s = GUS[e * 192 + (r0 >> 7) * 12 + (c0 >> 7)];
#pragma unroll
    for (int i = 0; i < 4; i++) t[ty + 8 * i][tx] = src[(size_t)(ty + 8 * i) * TWOI + tx];
    __syncthreads();
    float* dst = O + ((size_t)e * TWOI + c0) * H_ + r0;
#pragma unroll
    for (int i = 0; i < 4; i++)
        dst[(size_t)(ty + 8 * i) * H_ + tx] = __uint_as_float(f2tf(t[tx][ty + 8 * i] * s));
}
__global__ void tr_dn(const float* __restrict__ DN, const float* __restrict__ DNS,
                      float* __restrict__ O) {
    __shared__ float t[32][33];
    const int tx = threadIdx.x, ty = threadIdx.y;
    const int c0 = blockIdx.x * 32, r0 = blockIdx.y * 32;   // r0: ei dim, c0: h dim
    const float* src = DN + (size_t)r0 * H_ + c0;
    const float s = DNS[(r0 / I_) * 96 + ((r0 % I_) >> 7) * 16 + (c0 >> 7)];
#pragma unroll
    for (int i = 0; i < 4; i++) t[ty + 8 * i][tx] = src[(size_t)(ty + 8 * i) * H_ + tx];
    __syncthreads();
    float* dst = O + (size_t)c0 * K2DIM + r0;
#pragma unroll
    for (int i = 0; i < 4; i++)
        dst[(size_t)(ty + 8 * i) * K2DIM + tx] = __uint_as_float(f2tf(t[tx][ty + 8 * i] * s));
}
__global__ void cv_x(const float* __restrict__ X, float* __restrict__ O) {
    const size_t i = (size_t)blockIdx.x * 256 + threadIdx.x;
    float4 v = reinterpret_cast<const float4*>(X)[i];
    float4 o;
    o.x = __uint_as_float(f2tf(v.x)); o.y = __uint_as_float(f2tf(v.y));
    o.z = __uint_as_float(f2tf(v.z)); o.w = __uint_as_float(f2tf(v.w));
    reinterpret_cast<float4*>(O)[i] = o;
}

// ---------------- main GEMM ----------------
// MODE 1: inter = rw*up*silu(gate); A=g_xt[T,2048], B=g_gut rows (gate/up interleaved)
// MODE 2: OUT = inter @ DN';        A=g_inter[T,12288], B=g_dnt[2048,12288]
template<int MODE>
__global__ void __launch_bounds__(256)
moe_mma(const float* __restrict__ RW, float* __restrict__ OUT)
{
    extern __shared__ char smraw[];
    const uint32_t sbase = (uint32_t)__cvta_generic_to_shared(smraw);
    const uint32_t sA = sbase, sB = sbase + STAGES * A_STAGE;

    const int tid = threadIdx.x, lane = tid & 31, wid = tid >> 5;
    const int warp_m = wid & 1, warp_n = wid >> 1;
    const int m0 = blockIdx.x * 128;

    int e = 0, j0 = 0, n0 = 0;
    const float *Ap, *Bp;
    int lda, ldb, NC;
    size_t brow;
    if (MODE == 1) {
        e = blockIdx.y / 6; j0 = (blockIdx.y % 6) * 128;
        Ap = g_xt; lda = H_; Bp = g_gut; ldb = H_; NC = H_ / KC;
        const int r = tid, i = r >> 4, sub = (r >> 3) & 1, o = r & 7;
        brow = (size_t)e * TWOI + sub * I_ + j0 + i * 8 + o;
    } else {
        n0 = blockIdx.y * 256;
        Ap = g_inter; lda = K2DIM; Bp = g_dnt; ldb = K2DIM; NC = K2DIM / KC;
        brow = (size_t)(n0 + tid);
    }
    const float* bsrc = Bp + brow * ldb;
    const int arow = tid >> 1, aq0 = (tid & 1) * 4;
    const float* asrc = Ap + (size_t)(m0 + arow) * lda + aq0 * 4;

    const int mat = lane >> 3, q = lane & 7;
    const int rA = (mat & 1) * 8 + q, aSeg = mat >> 1;
    const int rB = (mat >> 1) * 8 + q, bSeg = mat & 1;

    float acc[4][8][4];
#pragma unroll
    for (int a = 0; a < 4; a++)
#pragma unroll
        for (int b = 0; b < 8; b++)
#pragma unroll
            for (int c = 0; c < 4; c++) acc[a][b][c] = 0.f;

    auto ISSUE = [&](int c, int slot) {
        const uint32_t ab = sA + slot * A_STAGE;
        const float* as = asrc + c * KC;
#pragma unroll
        for (int i = 0; i < 4; i++) cp16(smad(ab, arow, aq0 + i), as + 4 * i);
        const uint32_t bb = sB + slot * B_STAGE;
        const float* bs = bsrc + c * KC;
#pragma unroll
        for (int i = 0; i < 8; i++) cp16(smad(bb, tid, i), bs + 4 * i);
        asm volatile("cp.async.commit_group;" ::: "memory");
    };
    auto COMPUTE = [&](int slot) {
        const uint32_t ab = sA + slot * A_STAGE, bb = sB + slot * B_STAGE;
#pragma unroll
        for (int s = 0; s < 4; s++) {
            uint32_t af[4][4], bf[4][4];
#pragma unroll
            for (int mi = 0; mi < 4; mi++)
                ldsm4(af[mi], smad(ab, warp_m * 64 + mi * 16 + rA, 2 * s + aSeg));
#pragma unroll
            for (int np = 0; np < 4; np++)
                ldsm4(bf[np], smad(bb, warp_n * 64 + np * 16 + rB, 2 * s + bSeg));
#pragma unroll
            for (int mi = 0; mi < 4; mi++)
#pragma unroll
                for (int nt = 0; nt < 8; nt++)
                    mma_tf32(acc[mi][nt], af[mi], bf[nt >> 1][(nt & 1) * 2], bf[nt >> 1][(nt & 1) * 2 + 1]);
        }
    };

    ISSUE(0, 0); ISSUE(1, 1);
    int cs = 0, is = 2;
#pragma unroll 1
    for (int c = 0; c < NC; c++) {
        asm volatile("cp.async.wait_group 1;" ::: "memory");
        __syncthreads();
        if (c + 2 < NC) {
            ISSUE(c + 2, is);
            if (++is == STAGES) is = 0;
        }
        COMPUTE(cs);
        if (++cs == STAGES) cs = 0;
    }

    const int g = lane >> 2, tg = lane & 3;
    if (MODE == 1) {
#pragma unroll
        for (int mi = 0; mi < 4; mi++) {
            const int r0 = m0 + warp_m * 64 + mi * 16 + g, r1 = r0 + 8;
            const float rw0 = RW[r0 * E_ + e], rw1 = RW[r1 * E_ + e];
#pragma unroll
            for (int p = 0; p < 4; p++) {
                const float* gv = acc[mi][2 * p];
                const float* uv = acc[mi][2 * p + 1];
                const size_t col = (size_t)e * I_ + j0 + warp_n * 32 + p * 8 + tg * 2;
                float2 v;
                float x0 = rw0 * uv[0] * gv[0] / (1.f + __expf(-gv[0]));
                float x1 = rw0 * uv[1] * gv[1] / (1.f + __expf(-gv[1]));
                v.x = __uint_as_float(f2tf(x0)); v.y = __uint_as_float(f2tf(x1));
                *reinterpret_cast<float2*>(g_inter + (size_t)r0 * K2DIM + col) = v;
                x0 = rw1 * uv[2] * gv[2] / (1.f + __expf(-gv[2]));
                x1 = rw1 * uv[3] * gv[3] / (1.f + __expf(-gv[3]));
                v.x = __uint_as_float(f2tf(x0)); v.y = __uint_as_float(f2tf(x1));
                *reinterpret_cast<float2*>(g_inter + (size_t)r1 * K2DIM + col) = v;
            }
        }
    } else {
#pragma unroll
        for (int mi = 0; mi < 4; mi++) {
            const int r0 = m0 + warp_m * 64 + mi * 16 + g, r1 = r0 + 8;
#pragma unroll
            for (int nt = 0; nt < 8; nt++) {
                const size_t col = (size_t)n0 + warp_n * 64 + nt * 8 + tg * 2;
                float2 v;
                v.x = acc[mi][nt][0]; v.y = acc[mi][nt][1];
                *reinterpret_cast<float2*>(OUT + (size_t)r0 * H_ + col) = v;
                v.x = acc[mi][nt][2]; v.y = acc[mi][nt][3];
                *reinterpret_cast<float2*>(OUT + (size_t)r1 * H_ + col) = v;
            }
        }
    }
}

extern "C" void kernel_launch(void* const* d_in, const int* in_sizes, int n_in,
                              void* d_out, int out_size) {
    (void)in_sizes; (void)n_in; (void)out_size;
    const float* X   = (const float*)d_in[0];
    const float* RW  = (const float*)d_in[1];
    const float* GU  = (const float*)d_in[2];
    const float* GUS = (const float*)d_in[3];
    const float* DN  = (const float*)d_in[4];
    const float* DNS = (const float*)d_in[5];
    float* OUT = (float*)d_out;

    float *p_gut, *p_dnt, *p_xt;
    cudaGetSymbolAddress((void**)&p_gut, g_gut);
    cudaGetSymbolAddress((void**)&p_dnt, g_dnt);
    cudaGetSymbolAddress((void**)&p_xt,  g_xt);

    tr_gu<<<dim3(TWOI / 32, H_ / 32, E_), dim3(32, 8)>>>(GU, GUS, p_gut);
    tr_dn<<<dim3(H_ / 32, K2DIM / 32), dim3(32, 8)>>>(DN, DNS, p_dnt);
    cv_x<<<(int)((size_t)T_ * H_ / 1024), 256>>>(X, p_xt);

    cudaFuncSetAttribute(moe_mma<1>, cudaFuncAttributeMaxDynamicSharedMemorySize, SMEM_BYTES);
    cudaFuncSetAttribute(moe_mma<2>, cudaFuncAttributeMaxDynamicSharedMemorySize, SMEM_BYTES);

    moe_mma<1><<<dim3(32, 96), 256, SMEM_BYTES>>>(RW, nullptr);
    moe_mma<2><<<dim3(32, 8), 256, SMEM_BYTES>>>(nullptr, OUT);
}

// round 7
// speedup vs baseline: 2.0171x; 1.6765x over previous
#include <cuda_runtime.h>
#include <stdint.h>
#include <math.h>

#define E_ 16
#define H_ 2048
#define I_ 768
#define TWOI 1536
#define T_ 4096
#define K2DIM 12288
#define KC 32
#define STAGES 3

#define A_STAGE (128*128)
#define B_STAGE (128*128)
#define SMEM_BYTES (STAGES*(A_STAGE+B_STAGE))   // 98304 (96KB) -> 2 CTAs/SM

__device__ float g_inter[(size_t)T_ * K2DIM];    // [T][E*I]  tf32 values
__device__ float g_gut [(size_t)E_ * TWOI * H_]; // [e][j'][h] scaled tf32 (j'<768 gate else up)
__device__ float g_dnt [(size_t)H_ * K2DIM];     // [h][e*I+i] scaled tf32
__device__ float g_xt  [(size_t)T_ * H_];        // tf32(X)

static __device__ __forceinline__ uint32_t f2tf(float x) {
    uint32_t u; asm("cvt.rna.tf32.f32 %0, %1;" : "=r"(u) : "f"(x)); return u;
}
static __device__ __forceinline__ void ldsm4(uint32_t r[4], uint32_t a) {
    asm volatile("ldmatrix.sync.aligned.m8n8.x4.shared.b16 {%0,%1,%2,%3}, [%4];"
                 : "=r"(r[0]), "=r"(r[1]), "=r"(r[2]), "=r"(r[3]) : "r"(a));
}
static __device__ __forceinline__ void cp16(uint32_t d, const void* s) {
    asm volatile("cp.async.cg.shared.global [%0], [%1], 16;" :: "r"(d), "l"(s) : "memory");
}
static __device__ __forceinline__ void mma_tf32(float c[4], const uint32_t a[4], uint32_t b0, uint32_t b1) {
    asm volatile("mma.sync.aligned.m16n8k8.row.col.f32.tf32.tf32.f32 "
                 "{%0,%1,%2,%3}, {%4,%5,%6,%7}, {%8,%9}, {%0,%1,%2,%3};"
                 : "+f"(c[0]), "+f"(c[1]), "+f"(c[2]), "+f"(c[3])
                 : "r"(a[0]), "r"(a[1]), "r"(a[2]), "r"(a[3]), "r"(b0), "r"(b1));
}
// row r, 16B quad qd; XOR swizzle: conflict-free for cp.async writes + ldmatrix reads
static __device__ __forceinline__ uint32_t smad(uint32_t base, int r, int qd) {
    return base + (uint32_t)r * 128u + (uint32_t)((qd ^ (r & 7)) << 4);
}

// ---------------- preprocessing ----------------
__global__ void tr_gu(const float* __restrict__ GU, const float* __restrict__ GUS,
                      float* __restrict__ O) {
    __shared__ float t[32][33];
    const int tx = threadIdx.x, ty = threadIdx.y;
    const int c0 = blockIdx.x * 32, r0 = blockIdx.y * 32, e = blockIdx.z;
    const float* src = GU + ((size_t)e * H_ + r0) * TWOI + c0;
    const float s = GUS[e * 192 + (r0 >> 7) * 12 + (c0 >> 7)];
#pragma unroll
    for (int i = 0; i < 4; i++) t[ty + 8 * i][tx] = src[(size_t)(ty + 8 * i) * TWOI + tx];
    __syncthreads();
    float* dst = O + ((size_t)e * TWOI + c0) * H_ + r0;
#pragma unroll
    for (int i = 0; i < 4; i++)
        dst[(size_t)(ty + 8 * i) * H_ + tx] = __uint_as_float(f2tf(t[tx][ty + 8 * i] * s));
}
__global__ void tr_dn(const float* __restrict__ DN, const float* __restrict__ DNS,
                      float* __restrict__ O) {
    __shared__ float t[32][33];
    const int tx = threadIdx.x, ty = threadIdx.y;
    const int c0 = blockIdx.x * 32, r0 = blockIdx.y * 32;   // r0: ei, c0: h
    const float* src = DN + (size_t)r0 * H_ + c0;
    const float s = DNS[(r0 / I_) * 96 + ((r0 % I_) >> 7) * 16 + (c0 >> 7)];
#pragma unroll
    for (int i = 0; i < 4; i++) t[ty + 8 * i][tx] = src[(size_t)(ty + 8 * i) * H_ + tx];
    __syncthreads();
    float* dst = O + (size_t)c0 * K2DIM + r0;
#pragma unroll
    for (int i = 0; i < 4; i++)
        dst[(size_t)(ty + 8 * i) * K2DIM + tx] = __uint_as_float(f2tf(t[tx][ty + 8 * i] * s));
}
__global__ void cv_x(const float* __restrict__ X, float* __restrict__ O) {
    const size_t i = (size_t)blockIdx.x * 256 + threadIdx.x;
    float4 v = reinterpret_cast<const float4*>(X)[i];
    float4 o;
    o.x = __uint_as_float(f2tf(v.x)); o.y = __uint_as_float(f2tf(v.y));
    o.z = __uint_as_float(f2tf(v.z)); o.w = __uint_as_float(f2tf(v.w));
    reinterpret_cast<float4*>(O)[i] = o;
}

// ---------------- main GEMM: CTA 128x128, 4 warps (2m x 2n), 64x64 warp tiles
// MODE 1: inter = rw*up*silu(gate); A=g_xt, B=g_gut rows interleaved gate/up
// MODE 2: OUT = inter @ DN';        A=g_inter, B=g_dnt
template<int MODE>
__global__ void __launch_bounds__(128, 2)
moe_mma(const float* __restrict__ RW, float* __restrict__ OUT)
{
    extern __shared__ char smraw[];
    const uint32_t sbase = (uint32_t)__cvta_generic_to_shared(smraw);
    const uint32_t sA = sbase, sB = sbase + STAGES * A_STAGE;

    const int tid = threadIdx.x, lane = tid & 31, wid = tid >> 5;
    const int warp_m = wid & 1, warp_n = wid >> 1;   // 2 x 2
    const int m0 = blockIdx.x * 128;

    int e = 0, j0 = 0, n0 = 0;
    const float *Ap, *Bp;
    int lda, ldb, NC;
    if (MODE == 1) {
        e = blockIdx.y / 12; j0 = (blockIdx.y % 12) * 64;
        Ap = g_xt; lda = H_; Bp = g_gut; ldb = H_; NC = H_ / KC;
    } else {
        n0 = blockIdx.y * 128;
        Ap = g_inter; lda = K2DIM; Bp = g_dnt; ldb = K2DIM; NC = K2DIM / KC;
    }

    // ---- producers: quad q8 per thread, rows r0r + 16*i (i=0..7)
    const int q8 = tid & 7, r0r = tid >> 3;          // r0r 0..15
    const uint32_t sw16 = (uint32_t)((q8 ^ (r0r & 7)) << 4);
    const uint32_t prow = (uint32_t)r0r * 128u + sw16;
    const float* aptr = Ap + (size_t)(m0 + r0r) * lda + q8 * 4;
    const float* bptr;
    int bstep;   // global row step per i
    if (MODE == 1) {
        // smem row rr = r0r+16i: sub=(r0r>>3)&1 (gate/up), o=r0r&7, block=i
        const int sub = (r0r >> 3) & 1, o = r0r & 7;
        bptr = Bp + (size_t)((size_t)e * TWOI + sub * I_ + j0 + o) * ldb + q8 * 4;
        bstep = 8;
    } else {
        bptr = Bp + (size_t)(n0 + r0r) * ldb + q8 * 4;
        bstep = 16;
    }

    // ---- ldmatrix lane constants
    const int mat = lane >> 3, qq = lane & 7;
    const int rA = (mat & 1) * 8 + qq, aSeg = mat >> 1;
    const int rB = (mat >> 1) * 8 + qq, bSeg = mat & 1;

    float acc[4][8][4];
#pragma unroll
    for (int a = 0; a < 4; a++)
#pragma unroll
        for (int b = 0; b < 8; b++)
#pragma unroll
            for (int c = 0; c < 4; c++) acc[a][b][c] = 0.f;

    auto ISSUE = [&](int c, int slot) {
        const int k0 = c * KC;
        const uint32_t ab = sA + slot * A_STAGE + prow;
        const uint32_t bb = sB + slot * B_STAGE + prow;
#pragma unroll
        for (int i = 0; i < 8; i++) {
            cp16(ab + i * 2048u, aptr + (size_t)(16 * i) * lda + k0);
            cp16(bb + i * 2048u, bptr + (size_t)(bstep * i) * ldb + k0);
        }
        asm volatile("cp.async.commit_group;" ::: "memory");
    };
    auto COMPUTE = [&](int slot) {
        const uint32_t ab = sA + slot * A_STAGE, bb = sB + slot * B_STAGE;
#pragma unroll
        for (int s = 0; s < 4; s++) {
            uint32_t af[4][4], bf[4][4];
#pragma unroll
            for (int mi = 0; mi < 4; mi++)
                ldsm4(af[mi], smad(ab, warp_m * 64 + mi * 16 + rA, 2 * s + aSeg));
#pragma unroll
            for (int np = 0; np < 4; np++)
                ldsm4(bf[np], smad(bb, warp_n * 64 + np * 16 + rB, 2 * s + bSeg));
#pragma unroll
            for (int mi = 0; mi < 4; mi++)
#pragma unroll
                for (int nt = 0; nt < 8; nt++)
                    mma_tf32(acc[mi][nt], af[mi], bf[nt >> 1][(nt & 1) * 2], bf[nt >> 1][(nt & 1) * 2 + 1]);
        }
    };

    ISSUE(0, 0); ISSUE(1, 1);
    int cs = 0, is = 2;
#pragma unroll 1
    for (int c = 0; c < NC; c++) {
        asm volatile("cp.async.wait_group 1;" ::: "memory");
        __syncthreads();
        if (c + 2 < NC) {
            ISSUE(c + 2, is);
            if (++is == STAGES) is = 0;
        }
        COMPUTE(cs);
        if (++cs == STAGES) cs = 0;
    }

    // ---- epilogue
    const int g = lane >> 2, tg = lane & 3;
    if (MODE == 1) {
#pragma unroll
        for (int mi = 0; mi < 4; mi++) {
            const int r0 = m0 + warp_m * 64 + mi * 16 + g, r1 = r0 + 8;
            const float rw0 = RW[r0 * E_ + e], rw1 = RW[r1 * E_ + e];
#pragma unroll
            for (int p = 0; p < 4; p++) {
                const float* gv = acc[mi][2 * p];       // gate: even 8-row groups
                const float* uv = acc[mi][2 * p + 1];   // up: odd
                const size_t col = (size_t)e * I_ + j0 + warp_n * 32 + p * 8 + tg * 2;
                float2 v;
                float x0 = rw0 * uv[0] * gv[0] / (1.f + __expf(-gv[0]));
                float x1 = rw0 * uv[1] * gv[1] / (1.f + __expf(-gv[1]));
                v.x = __uint_as_float(f2tf(x0)); v.y = __uint_as_float(f2tf(x1));
                *reinterpret_cast<float2*>(g_inter + (size_t)r0 * K2DIM + col) = v;
                x0 = rw1 * uv[2] * gv[2] / (1.f + __expf(-gv[2]));
                x1 = rw1 * uv[3] * gv[3] / (1.f + __expf(-gv[3]));
                v.x = __uint_as_float(f2tf(x0)); v.y = __uint_as_float(f2tf(x1));
                *reinterpret_cast<float2*>(g_inter + (size_t)r1 * K2DIM + col) = v;
            }
        }
    } else {
#pragma unroll
        for (int mi = 0; mi < 4; mi++) {
            const int r0 = m0 + warp_m * 64 + mi * 16 + g, r1 = r0 + 8;
#pragma unroll
            for (int nt = 0; nt < 8; nt++) {
                const size_t col = (size_t)n0 + warp_n * 64 + nt * 8 + tg * 2;
                float2 v;
                v.x = acc[mi][nt][0]; v.y = acc[mi][nt][1];
                *reinterpret_cast<float2*>(OUT + (size_t)r0 * H_ + col) = v;
                v.x = acc[mi][nt][2]; v.y = acc[mi][nt][3];
                *reinterpret_cast<float2*>(OUT + (size_t)r1 * H_ + col) = v;
            }
        }
    }
}

extern "C" void kernel_launch(void* const* d_in, const int* in_sizes, int n_in,
                              void* d_out, int out_size) {
    (void)in_sizes; (void)n_in; (void)out_size;
    const float* X   = (const float*)d_in[0];
    const float* RW  = (const float*)d_in[1];
    const float* GU  = (const float*)d_in[2];
    const float* GUS = (const float*)d_in[3];
    const float* DN  = (const float*)d_in[4];
    const float* DNS = (const float*)d_in[5];
    float* OUT = (float*)d_out;

    float *p_gut, *p_dnt, *p_xt;
    cudaGetSymbolAddress((void**)&p_gut, g_gut);
    cudaGetSymbolAddress((void**)&p_dnt, g_dnt);
    cudaGetSymbolAddress((void**)&p_xt,  g_xt);

    tr_gu<<<dim3(TWOI / 32, H_ / 32, E_), dim3(32, 8)>>>(GU, GUS, p_gut);
    tr_dn<<<dim3(H_ / 32, K2DIM / 32), dim3(32, 8)>>>(DN, DNS, p_dnt);
    cv_x<<<(int)((size_t)T_ * H_ / 1024), 256>>>(X, p_xt);

    cudaFuncSetAttribute(moe_mma<1>, cudaFuncAttributeMaxDynamicSharedMemorySize, SMEM_BYTES);
    cudaFuncSetAttribute(moe_mma<2>, cudaFuncAttributeMaxDynamicSharedMemorySize, SMEM_BYTES);

    moe_mma<1><<<dim3(32, 192), 128, SMEM_BYTES>>>(RW, nullptr);
    moe_mma<2><<<dim3(32, 16), 128, SMEM_BYTES>>>(nullptr, OUT);
}

// round 8
// speedup vs baseline: 2.0273x; 1.0051x over previous
#include <cuda_runtime.h>
#include <stdint.h>
#include <math.h>

#define E_ 16
#define H_ 2048
#define I_ 768
#define TWOI 1536
#define T_ 4096
#define K2DIM 12288
#define KC 32
#define STAGES 2

#define A_STAGE (128*128)
#define B_STAGE (128*128)
#define SMEM_BYTES (STAGES*(A_STAGE+B_STAGE))   // 65536 -> 3 CTAs/SM

__device__ float g_inter[(size_t)T_ * K2DIM];    // [T][E*I]  tf32 values
__device__ float g_gut [(size_t)E_ * TWOI * H_]; // [e][j'][h] scaled tf32 (j'<768 gate else up)
__device__ float g_dnt [(size_t)H_ * K2DIM];     // [h][e*I+i] scaled tf32
__device__ float g_xt  [(size_t)T_ * H_];        // tf32(X)

static __device__ __forceinline__ uint32_t f2tf(float x) {
    uint32_t u; asm("cvt.rna.tf32.f32 %0, %1;" : "=r"(u) : "f"(x)); return u;
}
static __device__ __forceinline__ void ldsm4(uint32_t r[4], uint32_t a) {
    asm volatile("ldmatrix.sync.aligned.m8n8.x4.shared.b16 {%0,%1,%2,%3}, [%4];"
                 : "=r"(r[0]), "=r"(r[1]), "=r"(r[2]), "=r"(r[3]) : "r"(a));
}
static __device__ __forceinline__ void cp16(uint32_t d, const void* s) {
    asm volatile("cp.async.cg.shared.global [%0], [%1], 16;" :: "r"(d), "l"(s) : "memory");
}
static __device__ __forceinline__ void mma_tf32(float c[4], const uint32_t a[4], uint32_t b0, uint32_t b1) {
    asm volatile("mma.sync.aligned.m16n8k8.row.col.f32.tf32.tf32.f32 "
                 "{%0,%1,%2,%3}, {%4,%5,%6,%7}, {%8,%9}, {%0,%1,%2,%3};"
                 : "+f"(c[0]), "+f"(c[1]), "+f"(c[2]), "+f"(c[3])
                 : "r"(a[0]), "r"(a[1]), "r"(a[2]), "r"(a[3]), "r"(b0), "r"(b1));
}
// row r, 16B quad qd; XOR swizzle: conflict-free for cp.async writes + ldmatrix reads
static __device__ __forceinline__ uint32_t smad(uint32_t base, int r, int qd) {
    return base + (uint32_t)r * 128u + (uint32_t)((qd ^ (r & 7)) << 4);
}

// ---------------- preprocessing ----------------
__global__ void tr_gu(const float* __restrict__ GU, const float* __restrict__ GUS,
                      float* __restrict__ O) {
    __shared__ float t[32][33];
    const int tx = threadIdx.x, ty = threadIdx.y;
    const int c0 = blockIdx.x * 32, r0 = blockIdx.y * 32, e = blockIdx.z;
    const float* src = GU + ((size_t)e * H_ + r0) * TWOI + c0;
    const float s = GUS[e * 192 + (r0 >> 7) * 12 + (c0 >> 7)];
#pragma unroll
    for (int i = 0; i < 4; i++) t[ty + 8 * i][tx] = src[(size_t)(ty + 8 * i) * TWOI + tx];
    __syncthreads();
    float* dst = O + ((size_t)e * TWOI + c0) * H_ + r0;
#pragma unroll
    for (int i = 0; i < 4; i++)
        dst[(size_t)(ty + 8 * i) * H_ + tx] = __uint_as_float(f2tf(t[tx][ty + 8 * i] * s));
}
__global__ void tr_dn(const float* __restrict__ DN, const float* __restrict__ DNS,
                      float* __restrict__ O) {
    __shared__ float t[32][33];
    const int tx = threadIdx.x, ty = threadIdx.y;
    const int c0 = blockIdx.x * 32, r0 = blockIdx.y * 32;   // r0: ei, c0: h
    const float* src = DN + (size_t)r0 * H_ + c0;
    const float s = DNS[(r0 / I_) * 96 + ((r0 % I_) >> 7) * 16 + (c0 >> 7)];
#pragma unroll
    for (int i = 0; i < 4; i++) t[ty + 8 * i][tx] = src[(size_t)(ty + 8 * i) * H_ + tx];
    __syncthreads();
    float* dst = O + (size_t)c0 * K2DIM + r0;
#pragma unroll
    for (int i = 0; i < 4; i++)
        dst[(size_t)(ty + 8 * i) * K2DIM + tx] = __uint_as_float(f2tf(t[tx][ty + 8 * i] * s));
}
__global__ void cv_x(const float* __restrict__ X, float* __restrict__ O) {
    const size_t i = (size_t)blockIdx.x * 256 + threadIdx.x;
    float4 v = reinterpret_cast<const float4*>(X)[i];
    float4 o;
    o.x = __uint_as_float(f2tf(v.x)); o.y = __uint_as_float(f2tf(v.y));
    o.z = __uint_as_float(f2tf(v.z)); o.w = __uint_as_float(f2tf(v.w));
    reinterpret_cast<float4*>(O)[i] = o;
}

// ---------------- main GEMM: CTA 128x128, 4 warps (2m x 2n), 64x64 warp tiles
// MODE 1: inter = rw*up*silu(gate); A=g_xt, B=g_gut rows interleaved gate/up
// MODE 2: OUT = inter @ DN';        A=g_inter, B=g_dnt
template<int MODE>
__global__ void __launch_bounds__(128, 3)
moe_mma(const float* __restrict__ RW, float* __restrict__ OUT)
{
    extern __shared__ char smraw[];
    const uint32_t sbase = (uint32_t)__cvta_generic_to_shared(smraw);
    const uint32_t sA = sbase, sB = sbase + STAGES * A_STAGE;

    const int tid = threadIdx.x, lane = tid & 31, wid = tid >> 5;
    const int warp_m = wid & 1, warp_n = wid >> 1;   // 2 x 2
    const int m0 = blockIdx.x * 128;

    int e = 0, j0 = 0, n0 = 0;
    const float *Ap, *Bp;
    int lda, ldb, NC;
    if (MODE == 1) {
        e = blockIdx.y / 12; j0 = (blockIdx.y % 12) * 64;
        Ap = g_xt; lda = H_; Bp = g_gut; ldb = H_; NC = H_ / KC;
    } else {
        n0 = blockIdx.y * 128;
        Ap = g_inter; lda = K2DIM; Bp = g_dnt; ldb = K2DIM; NC = K2DIM / KC;
    }

    // ---- producers: quad q8 per thread, rows r0r + 16*i (i=0..7)
    const int q8 = tid & 7, r0r = tid >> 3;          // r0r 0..15
    const uint32_t prow = (uint32_t)r0r * 128u + (uint32_t)((q8 ^ (r0r & 7)) << 4);
    const float* aptr = Ap + (size_t)(m0 + r0r) * lda + q8 * 4;
    const float* bptr;
    int bstep;   // global row step per i
    if (MODE == 1) {
        const int sub = (r0r >> 3) & 1, o = r0r & 7;   // smem row r0r+16i: gate/up interleave
        bptr = Bp + (size_t)((size_t)e * TWOI + sub * I_ + j0 + o) * ldb + q8 * 4;
        bstep = 8;
    } else {
        bptr = Bp + (size_t)(n0 + r0r) * ldb + q8 * 4;
        bstep = 16;
    }

    // ---- ldmatrix lane constants
    const int mat = lane >> 3, qq = lane & 7;
    const int rA = (mat & 1) * 8 + qq, aSeg = mat >> 1;
    const int rB = (mat >> 1) * 8 + qq, bSeg = mat & 1;

    float acc[4][8][4];
#pragma unroll
    for (int a = 0; a < 4; a++)
#pragma unroll
        for (int b = 0; b < 8; b++)
#pragma unroll
            for (int c = 0; c < 4; c++) acc[a][b][c] = 0.f;

    auto ISSUE = [&](int c, int slot) {
        const int k0 = c * KC;
        const uint32_t ab = sA + slot * A_STAGE + prow;
        const uint32_t bb = sB + slot * B_STAGE + prow;
#pragma unroll
        for (int i = 0; i < 8; i++) {
            cp16(ab + i * 2048u, aptr + (size_t)(16 * i) * lda + k0);
            cp16(bb + i * 2048u, bptr + (size_t)(bstep * i) * ldb + k0);
        }
        asm volatile("cp.async.commit_group;" ::: "memory");
    };
    auto COMPUTE = [&](int slot) {
        const uint32_t ab = sA + slot * A_STAGE, bb = sB + slot * B_STAGE;
#pragma unroll
        for (int s = 0; s < 4; s++) {
            uint32_t bf[4][4];
#pragma unroll
            for (int np = 0; np < 4; np++)
                ldsm4(bf[np], smad(bb, warp_n * 64 + np * 16 + rB, 2 * s + bSeg));
#pragma unroll
            for (int mi = 0; mi < 4; mi++) {
                uint32_t af[4];
                ldsm4(af, smad(ab, warp_m * 64 + mi * 16 + rA, 2 * s + aSeg));
#pragma unroll
                for (int nt = 0; nt < 8; nt++)
                    mma_tf32(acc[mi][nt], af, bf[nt >> 1][(nt & 1) * 2], bf[nt >> 1][(nt & 1) * 2 + 1]);
            }
        }
    };

    ISSUE(0, 0); ISSUE(1, 1);
#pragma unroll 1
    for (int c = 0; c < NC; c++) {
        asm volatile("cp.async.wait_group 1;" ::: "memory");
        __syncthreads();
        COMPUTE(c & 1);
        __syncthreads();
        if (c + 2 < NC) ISSUE(c + 2, c & 1);
    }

    // ---- epilogue
    const int g = lane >> 2, tg = lane & 3;
    if (MODE == 1) {
#pragma unroll
        for (int mi = 0; mi < 4; mi++) {
            const int r0 = m0 + warp_m * 64 + mi * 16 + g, r1 = r0 + 8;
            const float rw0 = RW[r0 * E_ + e], rw1 = RW[r1 * E_ + e];
#pragma unroll
            for (int p = 0; p < 4; p++) {
                const float* gv = acc[mi][2 * p];       // gate: even 8-row groups
                const float* uv = acc[mi][2 * p + 1];   // up: odd
                const size_t col = (size_t)e * I_ + j0 + warp_n * 32 + p * 8 + tg * 2;
                float2 v;
                float x0 = rw0 * uv[0] * gv[0] / (1.f + __expf(-gv[0]));
                float x1 = rw0 * uv[1] * gv[1] / (1.f + __expf(-gv[1]));
                v.x = __uint_as_float(f2tf(x0)); v.y = __uint_as_float(f2tf(x1));
                *reinterpret_cast<float2*>(g_inter + (size_t)r0 * K2DIM + col) = v;
                x0 = rw1 * uv[2] * gv[2] / (1.f + __expf(-gv[2]));
                x1 = rw1 * uv[3] * gv[3] / (1.f + __expf(-gv[3]));
                v.x = __uint_as_float(f2tf(x0)); v.y = __uint_as_float(f2tf(x1));
                *reinterpret_cast<float2*>(g_inter + (size_t)r1 * K2DIM + col) = v;
            }
        }
    } else {
#pragma unroll
        for (int mi = 0; mi < 4; mi++) {
            const int r0 = m0 + warp_m * 64 + mi * 16 + g, r1 = r0 + 8;
#pragma unroll
            for (int nt = 0; nt < 8; nt++) {
                const size_t col = (size_t)n0 + warp_n * 64 + nt * 8 + tg * 2;
                float2 v;
                v.x = acc[mi][nt][0]; v.y = acc[mi][nt][1];
                *reinterpret_cast<float2*>(OUT + (size_t)r0 * H_ + col) = v;
                v.x = acc[mi][nt][2]; v.y = acc[mi][nt][3];
                *reinterpret_cast<float2*>(OUT + (size_t)r1 * H_ + col) = v;
            }
        }
    }
}

extern "C" void kernel_launch(void* const* d_in, const int* in_sizes, int n_in,
                              void* d_out, int out_size) {
    (void)in_sizes; (void)n_in; (void)out_size;
    const float* X   = (const float*)d_in[0];
    const float* RW  = (const float*)d_in[1];
    const float* GU  = (const float*)d_in[2];
    const float* GUS = (const float*)d_in[3];
    const float* DN  = (const float*)d_in[4];
    const float* DNS = (const float*)d_in[5];
    float* OUT = (float*)d_out;

    float *p_gut, *p_dnt, *p_xt;
    cudaGetSymbolAddress((void**)&p_gut, g_gut);
    cudaGetSymbolAddress((void**)&p_dnt, g_dnt);
    cudaGetSymbolAddress((void**)&p_xt,  g_xt);

    tr_gu<<<dim3(TWOI / 32, H_ / 32, E_), dim3(32, 8)>>>(GU, GUS, p_gut);
    tr_dn<<<dim3(H_ / 32, K2DIM / 32), dim3(32, 8)>>>(DN, DNS, p_dnt);
    cv_x<<<(int)((size_t)T_ * H_ / 1024), 256>>>(X, p_xt);

    cudaFuncSetAttribute(moe_mma<1>, cudaFuncAttributeMaxDynamicSharedMemorySize, SMEM_BYTES);
    cudaFuncSetAttribute(moe_mma<2>, cudaFuncAttributeMaxDynamicSharedMemorySize, SMEM_BYTES);

    moe_mma<1><<<dim3(32, 192), 128, SMEM_BYTES>>>(RW, nullptr);
    moe_mma<2><<<dim3(32, 16), 128, SMEM_BYTES>>>(nullptr, OUT);
}

// round 10
// speedup vs baseline: 3.8755x; 1.9116x over previous
#include <cuda_runtime.h>
#include <cuda_fp16.h>
#include <stdint.h>
#include <math.h>

#define E_ 16
#define H_ 2048
#define I_ 768
#define TWOI 1536
#define T_ 4096
#define K2DIM 12288
#define KC 64
#define STAGES 2

#define A_STAGE (128*128)   // 128 rows x 64 halves (128B)
#define B_STAGE (128*128)
#define SMEM_BYTES (STAGES*(A_STAGE+B_STAGE))   // 65536 -> 3 CTAs/SM

__device__ __half g_inter[(size_t)T_ * K2DIM];    // [T][E*I]
__device__ __half g_gut [(size_t)E_ * TWOI * H_]; // [e][j'][h] scaled (j'<768 gate else up)
__device__ __half g_dnt [(size_t)H_ * K2DIM];     // [h][e*I+i] scaled
__device__ __half g_xt  [(size_t)T_ * H_];        // fp16(X)

static __device__ __forceinline__ void ldsm4(uint32_t r[4], uint32_t a) {
    asm volatile("ldmatrix.sync.aligned.m8n8.x4.shared.b16 {%0,%1,%2,%3}, [%4];"
                 : "=r"(r[0]), "=r"(r[1]), "=r"(r[2]), "=r"(r[3]) : "r"(a));
}
static __device__ __forceinline__ void cp16(uint32_t d, const void* s) {
    asm volatile("cp.async.cg.shared.global [%0], [%1], 16;" :: "r"(d), "l"(s) : "memory");
}
static __device__ __forceinline__ void mma16816(float c[4], const uint32_t a[4], uint32_t b0, uint32_t b1) {
    asm volatile("mma.sync.aligned.m16n8k16.row.col.f32.f16.f16.f32 "
                 "{%0,%1,%2,%3}, {%4,%5,%6,%7}, {%8,%9}, {%0,%1,%2,%3};"
                 : "+f"(c[0]), "+f"(c[1]), "+f"(c[2]), "+f"(c[3])
                 : "r"(a[0]), "r"(a[1]), "r"(a[2]), "r"(a[3]), "r"(b0), "r"(b1));
}

// ---------------- preprocessing (fold scales, cast fp16, transpose weights) ----
__global__ void tr_gu(const float* __restrict__ GU, const float* __restrict__ GUS,
                      __half* __restrict__ O) {
    __shared__ float t[32][33];
    const int tx = threadIdx.x, ty = threadIdx.y;
    const int c0 = blockIdx.x * 32, r0 = blockIdx.y * 32, e = blockIdx.z;
    const float* src = GU + ((size_t)e * H_ + r0) * TWOI + c0;
    const float s = GUS[e * 192 + (r0 >> 7) * 12 + (c0 >> 7)];
#pragma unroll
    for (int i = 0; i < 4; i++) t[ty + 8 * i][tx] = src[(size_t)(ty + 8 * i) * TWOI + tx];
    __syncthreads();
    __half* dst = O + ((size_t)e * TWOI + c0) * H_ + r0;
#pragma unroll
    for (int i = 0; i < 4; i++)
        dst[(size_t)(ty + 8 * i) * H_ + tx] = __float2half_rn(t[tx][ty + 8 * i] * s);
}
__global__ void tr_dn(const float* __restrict__ DN, const float* __restrict__ DNS,
                      __half* __restrict__ O) {
    __shared__ float t[32][33];
    const int tx = threadIdx.x, ty = threadIdx.y;
    const int c0 = blockIdx.x * 32, r0 = blockIdx.y * 32;   // r0: ei, c0: h
    const float* src = DN + (size_t)r0 * H_ + c0;
    const float s = DNS[(r0 / I_) * 96 + ((r0 % I_) >> 7) * 16 + (c0 >> 7)];
#pragma unroll
    for (int i = 0; i < 4; i++) t[ty + 8 * i][tx] = src[(size_t)(ty + 8 * i) * H_ + tx];
    __syncthreads();
    __half* dst = O + (size_t)c0 * K2DIM + r0;
#pragma unroll
    for (int i = 0; i < 4; i++)
        dst[(size_t)(ty + 8 * i) * K2DIM + tx] = __float2half_rn(t[tx][ty + 8 * i] * s);
}
__global__ void cv_x(const float* __restrict__ X, __half* __restrict__ O) {
    const size_t i = (size_t)blockIdx.x * 256 + threadIdx.x;
    float4 v = reinterpret_cast<const float4*>(X)[i];
    __half2 h0 = __floats2half2_rn(v.x, v.y);
    __half2 h1 = __floats2half2_rn(v.z, v.w);
    __half2* dst = reinterpret_cast<__half2*>(O) + i * 2;
    dst[0] = h0;
    dst[1] = h1;
}

// ---------------- main GEMM: CTA 128x128, 4 warps (2m x 2n), 64x64 warp tiles, fp16
// MODE 1: inter = rw*up*silu(gate); A=g_xt, B=g_gut rows interleaved gate/up
// MODE 2: OUT = inter @ DN';        A=g_inter, B=g_dnt
template<int MODE>
__global__ void __launch_bounds__(128, 3)
moe_mma(const float* __restrict__ RW, float* __restrict__ OUT)
{
    extern __shared__ char smraw[];
    const uint32_t sbase = (uint32_t)__cvta_generic_to_shared(smraw);
    const uint32_t sA = sbase, sB = sbase + STAGES * A_STAGE;

    const int tid = threadIdx.x, lane = tid & 31, wid = tid >> 5;
    const int warp_m = wid & 1, warp_n = wid >> 1;   // 2 x 2
    const int m0 = blockIdx.x * 128;

    int e = 0, j0 = 0, n0 = 0;
    const __half *Ap, *Bp;
    int lda, ldb, NC;
    if (MODE == 1) {
        e = blockIdx.y / 12; j0 = (blockIdx.y % 12) * 64;
        Ap = g_xt; lda = H_; Bp = g_gut; ldb = H_; NC = H_ / KC;
    } else {
        n0 = blockIdx.y * 128;
        Ap = g_inter; lda = K2DIM; Bp = g_dnt; ldb = K2DIM; NC = K2DIM / KC;
    }

    // ---- producers: quad q8 (16B = 8 halves) per thread, rows r0r + 16*i
    const int q8 = tid & 7, r0r = tid >> 3;          // r0r 0..15
    const uint32_t prow = (uint32_t)r0r * 128u + (uint32_t)((q8 ^ (r0r & 7)) << 4);
    const __half* aptr = Ap + (size_t)(m0 + r0r) * lda + q8 * 8;
    const __half* bptr;
    int bstep;
    if (MODE == 1) {
        const int sub = (r0r >> 3) & 1, o = r0r & 7;   // gate/up interleave by 8-row groups
        bptr = Bp + (size_t)((size_t)e * TWOI + sub * I_ + j0 + o) * ldb + q8 * 8;
        bstep = 8;
    } else {
        bptr = Bp + (size_t)(n0 + r0r) * ldb + q8 * 8;
        bstep = 16;
    }

    // ---- ldmatrix lane constants (fragment rows all satisfy row&7 == qq)
    const int mat = lane >> 3, qq = lane & 7;
    const int rA = (mat & 1) * 8 + qq, aSeg = mat >> 1;
    const int rB = (mat >> 1) * 8 + qq, bSeg = mat & 1;
    uint32_t xa[4], xb[4];
#pragma unroll
    for (int s = 0; s < 4; s++) {
        xa[s] = (uint32_t)(((2 * s + aSeg) ^ qq) << 4);
        xb[s] = (uint32_t)(((2 * s + bSeg) ^ qq) << 4);
    }

    float acc[4][8][4];
#pragma unroll
    for (int a = 0; a < 4; a++)
#pragma unroll
        for (int b = 0; b < 8; b++)
#pragma unroll
            for (int c = 0; c < 4; c++) acc[a][b][c] = 0.f;

    auto ISSUE = [&](int c, int slot) {
        const int k0 = c * KC;
        const uint32_t ab = sA + slot * A_STAGE + prow;
        const uint32_t bb = sB + slot * B_STAGE + prow;
#pragma unroll
        for (int i = 0; i < 8; i++) {
            cp16(ab + i * 2048u, aptr + (size_t)(16 * i) * lda + k0);
            cp16(bb + i * 2048u, bptr + (size_t)(bstep * i) * ldb + k0);
        }
        asm volatile("cp.async.commit_group;" ::: "memory");
    };
    auto COMPUTE = [&](int slot) {
        const uint32_t ab = sA + slot * A_STAGE, bb = sB + slot * B_STAGE;
        uint32_t aRow[4], bRow[4];
#pragma unroll
        for (int mi = 0; mi < 4; mi++) aRow[mi] = ab + (uint32_t)(warp_m * 64 + mi * 16 + rA) * 128u;
#pragma unroll
        for (int np = 0; np < 4; np++) bRow[np] = bb + (uint32_t)(warp_n * 64 + np * 16 + rB) * 128u;
#pragma unroll
        for (int s = 0; s < 4; s++) {
            uint32_t bf[4][4];
#pragma unroll
            for (int np = 0; np < 4; np++) ldsm4(bf[np], bRow[np] + xb[s]);
#pragma unroll
            for (int mi = 0; mi < 4; mi++) {
                uint32_t af[4];
                ldsm4(af, aRow[mi] + xa[s]);
#pragma unroll
                for (int nt = 0; nt < 8; nt++)
                    mma16816(acc[mi][nt], af, bf[nt >> 1][(nt & 1) * 2], bf[nt >> 1][(nt & 1) * 2 + 1]);
            }
        }
    };

    ISSUE(0, 0); ISSUE(1, 1);
#pragma unroll 1
    for (int c = 0; c < NC; c++) {
        asm volatile("cp.async.wait_group 1;" ::: "memory");
        __syncthreads();
        COMPUTE(c & 1);
        __syncthreads();
        if (c + 2 < NC) ISSUE(c + 2, c & 1);
    }

    // ---- epilogue
    const int g = lane >> 2, tg = lane & 3;
    if (MODE == 1) {
#pragma unroll
        for (int mi = 0; mi < 4; mi++) {
            const int r0 = m0 + warp_m * 64 + mi * 16 + g, r1 = r0 + 8;
            const float rw0 = RW[r0 * E_ + e], rw1 = RW[r1 * E_ + e];
#pragma unroll
            for (int p = 0; p < 4; p++) {
                const float* gv = acc[mi][2 * p];       // gate: even 8-row groups
                const float* uv = acc[mi][2 * p + 1];   // up: odd
                const size_t col = (size_t)e * I_ + j0 + warp_n * 32 + p * 8 + tg * 2;
                float x0 = rw0 * uv[0] * gv[0] / (1.f + __expf(-gv[0]));
                float x1 = rw0 * uv[1] * gv[1] / (1.f + __expf(-gv[1]));
                *reinterpret_cast<__half2*>(g_inter + (size_t)r0 * K2DIM + col) = __floats2half2_rn(x0, x1);
                x0 = rw1 * uv[2] * gv[2] / (1.f + __expf(-gv[2]));
                x1 = rw1 * uv[3] * gv[3] / (1.f + __expf(-gv[3]));
                *reinterpret_cast<__half2*>(g_inter + (size_t)r1 * K2DIM + col) = __floats2half2_rn(x0, x1);
            }
        }
    } else {
#pragma unroll
        for (int mi = 0; mi < 4; mi++) {
            const int r0 = m0 + warp_m * 64 + mi * 16 + g, r1 = r0 + 8;
#pragma unroll
            for (int nt = 0; nt < 8; nt++) {
                const size_t col = (size_t)n0 + warp_n * 64 + nt * 8 + tg * 2;
                float2 v;
                v.x = acc[mi][nt][0]; v.y = acc[mi][nt][1];
                *reinterpret_cast<float2*>(OUT + (size_t)r0 * H_ + col) = v;
                v.x = acc[mi][nt][2]; v.y = acc[mi][nt][3];
                *reinterpret_cast<float2*>(OUT + (size_t)r1 * H_ + col) = v;
            }
        }
    }
}

extern "C" void kernel_launch(void* const* d_in, const int* in_sizes, int n_in,
                              void* d_out, int out_size) {
    (void)in_sizes; (void)n_in; (void)out_size;
    const float* X   = (const float*)d_in[0];
    const float* RW  = (const float*)d_in[1];
    const float* GU  = (const float*)d_in[2];
    const float* GUS = (const float*)d_in[3];
    const float* DN  = (const float*)d_in[4];
    const float* DNS = (const float*)d_in[5];
    float* OUT = (float*)d_out;

    __half *p_gut, *p_dnt, *p_xt;
    cudaGetSymbolAddress((void**)&p_gut, g_gut);
    cudaGetSymbolAddress((void**)&p_dnt, g_dnt);
    cudaGetSymbolAddress((void**)&p_xt,  g_xt);

    tr_gu<<<dim3(TWOI / 32, H_ / 32, E_), dim3(32, 8)>>>(GU, GUS, p_gut);
    tr_dn<<<dim3(H_ / 32, K2DIM / 32), dim3(32, 8)>>>(DN, DNS, p_dnt);
    cv_x<<<(int)((size_t)T_ * H_ / 1024), 256>>>(X, p_xt);

    cudaFuncSetAttribute(moe_mma<1>, cudaFuncAttributeMaxDynamicSharedMemorySize, SMEM_BYTES);
    cudaFuncSetAttribute(moe_mma<2>, cudaFuncAttributeMaxDynamicSharedMemorySize, SMEM_BYTES);

    moe_mma<1><<<dim3(32, 192), 128, SMEM_BYTES>>>(RW, nullptr);
    moe_mma<2><<<dim3(32, 16), 128, SMEM_BYTES>>>(nullptr, OUT);
}

// round 12
// speedup vs baseline: 3.9084x; 1.0085x over previous
#include <cuda_runtime.h>
#include <cuda_fp16.h>
#include <stdint.h>
#include <math.h>

#define E_ 16
#define H_ 2048
#define I_ 768
#define TWOI 1536
#define T_ 4096
#define K2DIM 12288
#define KC 64
#define STAGES 2

#define A_STAGE (128*128)   // 128 rows x 64 halves (128B)
#define B_STAGE (128*128)
#define SMEM_BYTES (STAGES*(A_STAGE+B_STAGE))   // 65536 -> 3 CTAs/SM

__device__ __half g_inter[(size_t)T_ * K2DIM];    // [T][E*I]
__device__ __half g_gut [(size_t)E_ * TWOI * H_]; // [e][j'][h] scaled (j'<768 gate else up)
__device__ __half g_dnt [(size_t)H_ * K2DIM];     // [h][e*I+i] scaled
__device__ __half g_xt  [(size_t)T_ * H_];        // fp16(X)

static __device__ __forceinline__ void ldsm4(uint32_t r[4], uint32_t a) {
    asm volatile("ldmatrix.sync.aligned.m8n8.x4.shared.b16 {%0,%1,%2,%3}, [%4];"
                 : "=r"(r[0]), "=r"(r[1]), "=r"(r[2]), "=r"(r[3]) : "r"(a));
}
static __device__ __forceinline__ void cp16(uint32_t d, const void* s) {
    asm volatile("cp.async.cg.shared.global [%0], [%1], 16;" :: "r"(d), "l"(s) : "memory");
}
static __device__ __forceinline__ void mma16816(float c[4], const uint32_t a[4], uint32_t b0, uint32_t b1) {
    asm volatile("mma.sync.aligned.m16n8k16.row.col.f32.f16.f16.f32 "
                 "{%0,%1,%2,%3}, {%4,%5,%6,%7}, {%8,%9}, {%0,%1,%2,%3};"
                 : "+f"(c[0]), "+f"(c[1]), "+f"(c[2]), "+f"(c[3])
                 : "r"(a[0]), "r"(a[1]), "r"(a[2]), "r"(a[3]), "r"(b0), "r"(b1));
}

// ---------------- preprocessing: 64x64 transpose tiles, fp16 out, 128B stores --
// Phase1: float4 coalesced loads into smem. Phase2: warp-per-output-row half2
// stores (32 lanes x 4B = full 128B line). Value-identical to the 32x32 version.
__global__ void tr_gu(const float* __restrict__ GU, const float* __restrict__ GUS,
                      __half* __restrict__ O) {
    __shared__ float t[64][65];
    const int tid = threadIdx.x;
    const int c0 = blockIdx.x * 64, r0 = blockIdx.y * 64, e = blockIdx.z; // c0: j, r0: h
    const float s = GUS[e * 192 + (r0 >> 7) * 12 + (c0 >> 7)];
    const float* src = GU + ((size_t)e * H_ + r0) * TWOI + c0;
    const int lr = tid >> 4, lq = tid & 15;
#pragma unroll
    for (int i = 0; i < 4; i++) {
        float4 v = *reinterpret_cast<const float4*>(src + (size_t)(lr + 16 * i) * TWOI + lq * 4);
        t[lr + 16 * i][lq * 4 + 0] = v.x; t[lr + 16 * i][lq * 4 + 1] = v.y;
        t[lr + 16 * i][lq * 4 + 2] = v.z; t[lr + 16 * i][lq * 4 + 3] = v.w;
    }
    __syncthreads();
    const int w = tid >> 5, l = tid & 31;
#pragma unroll
    for (int it = 0; it < 8; it++) {
        const int jj = w + 8 * it;
        __half2 v = __floats2half2_rn(t[2 * l][jj] * s, t[2 * l + 1][jj] * s);
        __half2* dst = reinterpret_cast<__half2*>(
            O + ((size_t)e * TWOI + c0 + jj) * H_ + r0);
        dst[l] = v;
    }
}
__global__ void tr_dn(const float* __restrict__ DN, const float* __restrict__ DNS,
                      __half* __restrict__ O) {
    __shared__ float t[64][65];
    const int tid = threadIdx.x;
    const int c0 = blockIdx.x * 64, r0 = blockIdx.y * 64;  // c0: h, r0: ei
    const float s = DNS[(r0 / I_) * 96 + ((r0 % I_) >> 7) * 16 + (c0 >> 7)];
    const float* src = DN + (size_t)r0 * H_ + c0;
    const int lr = tid >> 4, lq = tid & 15;
#pragma unroll
    for (int i = 0; i < 4; i++) {
        float4 v = *reinterpret_cast<const float4*>(src + (size_t)(lr + 16 * i) * H_ + lq * 4);
        t[lr + 16 * i][lq * 4 + 0] = v.x; t[lr + 16 * i][lq * 4 + 1] = v.y;
        t[lr + 16 * i][lq * 4 + 2] = v.z; t[lr + 16 * i][lq * 4 + 3] = v.w;
    }
    __syncthreads();
    const int w = tid >> 5, l = tid & 31;
#pragma unroll
    for (int it = 0; it < 8; it++) {
        const int jj = w + 8 * it;   // h index within tile
        __half2 v = __floats2half2_rn(t[2 * l][jj] * s, t[2 * l + 1][jj] * s);
        __half2* dst = reinterpret_cast<__half2*>(O + (size_t)(c0 + jj) * K2DIM + r0);
        dst[l] = v;
    }
}
__global__ void cv_x(const float* __restrict__ X, __half* __restrict__ O) {
    const size_t i = (size_t)blockIdx.x * 256 + threadIdx.x;
    float4 v = reinterpret_cast<const float4*>(X)[i];
    __half2* dst = reinterpret_cast<__half2*>(O) + i * 2;
    dst[0] = __floats2half2_rn(v.x, v.y);
    dst[1] = __floats2half2_rn(v.z, v.w);
}

// ---------------- main GEMM: CTA 128x128, 4 warps (2m x 2n), 64x64 warp tiles, fp16
// (byte-identical to the round-10 passing version)
// MODE 1: inter = rw*up*silu(gate); A=g_xt, B=g_gut rows interleaved gate/up
// MODE 2: OUT = inter @ DN';        A=g_inter, B=g_dnt
template<int MODE>
__global__ void __launch_bounds__(128, 3)
moe_mma(const float* __restrict__ RW, float* __restrict__ OUT)
{
    extern __shared__ char smraw[];
    const uint32_t sbase = (uint32_t)__cvta_generic_to_shared(smraw);
    const uint32_t sA = sbase, sB = sbase + STAGES * A_STAGE;

    const int tid = threadIdx.x, lane = tid & 31, wid = tid >> 5;
    const int warp_m = wid & 1, warp_n = wid >> 1;   // 2 x 2
    const int m0 = blockIdx.x * 128;

    int e = 0, j0 = 0, n0 = 0;
    const __half *Ap, *Bp;
    int lda, ldb, NC;
    if (MODE == 1) {
        e = blockIdx.y / 12; j0 = (blockIdx.y % 12) * 64;
        Ap = g_xt; lda = H_; Bp = g_gut; ldb = H_; NC = H_ / KC;
    } else {
        n0 = blockIdx.y * 128;
        Ap = g_inter; lda = K2DIM; Bp = g_dnt; ldb = K2DIM; NC = K2DIM / KC;
    }

    // ---- producers: quad q8 (16B = 8 halves) per thread, rows r0r + 16*i
    const int q8 = tid & 7, r0r = tid >> 3;          // r0r 0..15
    const uint32_t prow = (uint32_t)r0r * 128u + (uint32_t)((q8 ^ (r0r & 7)) << 4);
    const __half* aptr = Ap + (size_t)(m0 + r0r) * lda + q8 * 8;
    const __half* bptr;
    int bstep;
    if (MODE == 1) {
        const int sub = (r0r >> 3) & 1, o = r0r & 7;   // gate/up interleave by 8-row groups
        bptr = Bp + (size_t)((size_t)e * TWOI + sub * I_ + j0 + o) * ldb + q8 * 8;
        bstep = 8;
    } else {
        bptr = Bp + (size_t)(n0 + r0r) * ldb + q8 * 8;
        bstep = 16;
    }

    // ---- ldmatrix lane constants (fragment rows all satisfy row&7 == qq)
    const int mat = lane >> 3, qq = lane & 7;
    const int rA = (mat & 1) * 8 + qq, aSeg = mat >> 1;
    const int rB = (mat >> 1) * 8 + qq, bSeg = mat & 1;
    uint32_t xa[4], xb[4];
#pragma unroll
    for (int s = 0; s < 4; s++) {
        xa[s] = (uint32_t)(((2 * s + aSeg) ^ qq) << 4);
        xb[s] = (uint32_t)(((2 * s + bSeg) ^ qq) << 4);
    }

    float acc[4][8][4];
#pragma unroll
    for (int a = 0; a < 4; a++)
#pragma unroll
        for (int b = 0; b < 8; b++)
#pragma unroll
            for (int c = 0; c < 4; c++) acc[a][b][c] = 0.f;

    auto ISSUE = [&](int c, int slot) {
        const int k0 = c * KC;
        const uint32_t ab = sA + slot * A_STAGE + prow;
        const uint32_t bb = sB + slot * B_STAGE + prow;
#pragma unroll
        for (int i = 0; i < 8; i++) {
            cp16(ab + i * 2048u, aptr + (size_t)(16 * i) * lda + k0);
            cp16(bb + i * 2048u, bptr + (size_t)(bstep * i) * ldb + k0);
        }
        asm volatile("cp.async.commit_group;" ::: "memory");
    };
    auto COMPUTE = [&](int slot) {
        const uint32_t ab = sA + slot * A_STAGE, bb = sB + slot * B_STAGE;
        uint32_t aRow[4], bRow[4];
#pragma unroll
        for (int mi = 0; mi < 4; mi++) aRow[mi] = ab + (uint32_t)(warp_m * 64 + mi * 16 + rA) * 128u;
#pragma unroll
        for (int np = 0; np < 4; np++) bRow[np] = bb + (uint32_t)(warp_n * 64 + np * 16 + rB) * 128u;
#pragma unroll
        for (int s = 0; s < 4; s++) {
            uint32_t bf[4][4];
#pragma unroll
            for (int np = 0; np < 4; np++) ldsm4(bf[np], bRow[np] + xb[s]);
#pragma unroll
            for (int mi = 0; mi < 4; mi++) {
                uint32_t af[4];
                ldsm4(af, aRow[mi] + xa[s]);
#pragma unroll
                for (int nt = 0; nt < 8; nt++)
                    mma16816(acc[mi][nt], af, bf[nt >> 1][(nt & 1) * 2], bf[nt >> 1][(nt & 1) * 2 + 1]);
            }
        }
    };

    ISSUE(0, 0); ISSUE(1, 1);
#pragma unroll 1
    for (int c = 0; c < NC; c++) {
        asm volatile("cp.async.wait_group 1;" ::: "memory");
        __syncthreads();
        COMPUTE(c & 1);
        __syncthreads();
        if (c + 2 < NC) ISSUE(c + 2, c & 1);
    }

    // ---- epilogue
    const int g = lane >> 2, tg = lane & 3;
    if (MODE == 1) {
#pragma unroll
        for (int mi = 0; mi < 4; mi++) {
            const int r0 = m0 + warp_m * 64 + mi * 16 + g, r1 = r0 + 8;
            const float rw0 = RW[r0 * E_ + e], rw1 = RW[r1 * E_ + e];
#pragma unroll
            for (int p = 0; p < 4; p++) {
                const float* gv = acc[mi][2 * p];       // gate: even 8-row groups
                const float* uv = acc[mi][2 * p + 1];   // up: odd
                const size_t col = (size_t)e * I_ + j0 + warp_n * 32 + p * 8 + tg * 2;
                float x0 = rw0 * uv[0] * gv[0] / (1.f + __expf(-gv[0]));
                float x1 = rw0 * uv[1] * gv[1] / (1.f + __expf(-gv[1]));
                *reinterpret_cast<__half2*>(g_inter + (size_t)r0 * K2DIM + col) = __floats2half2_rn(x0, x1);
                x0 = rw1 * uv[2] * gv[2] / (1.f + __expf(-gv[2]));
                x1 = rw1 * uv[3] * gv[3] / (1.f + __expf(-gv[3]));
                *reinterpret_cast<__half2*>(g_inter + (size_t)r1 * K2DIM + col) = __floats2half2_rn(x0, x1);
            }
        }
    } else {
#pragma unroll
        for (int mi = 0; mi < 4; mi++) {
            const int r0 = m0 + warp_m * 64 + mi * 16 + g, r1 = r0 + 8;
#pragma unroll
            for (int nt = 0; nt < 8; nt++) {
                const size_t col = (size_t)n0 + warp_n * 64 + nt * 8 + tg * 2;
                float2 v;
                v.x = acc[mi][nt][0]; v.y = acc[mi][nt][1];
                *reinterpret_cast<float2*>(OUT + (size_t)r0 * H_ + col) = v;
                v.x = acc[mi][nt][2]; v.y = acc[mi][nt][3];
                *reinterpret_cast<float2*>(OUT + (size_t)r1 * H_ + col) = v;
            }
        }
    }
}

extern "C" void kernel_launch(void* const* d_in, const int* in_sizes, int n_in,
                              void* d_out, int out_size) {
    (void)in_sizes; (void)n_in; (void)out_size;
    const float* X   = (const float*)d_in[0];
    const float* RW  = (const float*)d_in[1];
    const float* GU  = (const float*)d_in[2];
    const float* GUS = (const float*)d_in[3];
    const float* DN  = (const float*)d_in[4];
    const float* DNS = (const float*)d_in[5];
    float* OUT = (float*)d_out;

    __half *p_gut, *p_dnt, *p_xt;
    cudaGetSymbolAddress((void**)&p_gut, g_gut);
    cudaGetSymbolAddress((void**)&p_dnt, g_dnt);
    cudaGetSymbolAddress((void**)&p_xt,  g_xt);

    tr_gu<<<dim3(TWOI / 64, H_ / 64, E_), 256>>>(GU, GUS, p_gut);
    tr_dn<<<dim3(H_ / 64, K2DIM / 64), 256>>>(DN, DNS, p_dnt);
    cv_x<<<(int)((size_t)T_ * H_ / 1024), 256>>>(X, p_xt);

    cudaFuncSetAttribute(moe_mma<1>, cudaFuncAttributeMaxDynamicSharedMemorySize, SMEM_BYTES);
    cudaFuncSetAttribute(moe_mma<2>, cudaFuncAttributeMaxDynamicSharedMemorySize, SMEM_BYTES);

    moe_mma<1><<<dim3(32, 192), 128, SMEM_BYTES>>>(RW, nullptr);
    moe_mma<2><<<dim3(32, 16), 128, SMEM_BYTES>>>(nullptr, OUT);
}

// round 13
// speedup vs baseline: 4.0524x; 1.0368x over previous
#include <cuda_runtime.h>
#include <cuda_fp16.h>
#include <stdint.h>
#include <math.h>

#define E_ 16
#define H_ 2048
#define I_ 768
#define TWOI 1536
#define T_ 4096
#define K2DIM 12288
#define KC 64
#define STAGES 2
#define KSPLIT 4

#define A_STAGE (128*128)   // 128 rows x 64 halves (128B)
#define B_STAGE (128*128)
#define SMEM_BYTES (STAGES*(A_STAGE+B_STAGE))   // 65536 -> 3 CTAs/SM

__device__ __half g_inter[(size_t)T_ * K2DIM];    // [T][E*I]
__device__ __half g_gut [(size_t)E_ * TWOI * H_]; // [e][j'][h] scaled (j'<768 gate else up)
__device__ __half g_dnt [(size_t)H_ * K2DIM];     // [h][e*I+i] scaled
__device__ __half g_xt  [(size_t)T_ * H_];        // fp16(X)
__device__ float  g_part[KSPLIT - 1][(size_t)T_ * H_]; // split-K partials (z=1..3)

static __device__ __forceinline__ void ldsm4(uint32_t r[4], uint32_t a) {
    asm volatile("ldmatrix.sync.aligned.m8n8.x4.shared.b16 {%0,%1,%2,%3}, [%4];"
                 : "=r"(r[0]), "=r"(r[1]), "=r"(r[2]), "=r"(r[3]) : "r"(a));
}
static __device__ __forceinline__ void cp16(uint32_t d, const void* s) {
    asm volatile("cp.async.cg.shared.global [%0], [%1], 16;" :: "r"(d), "l"(s) : "memory");
}
static __device__ __forceinline__ void mma16816(float c[4], const uint32_t a[4], uint32_t b0, uint32_t b1) {
    asm volatile("mma.sync.aligned.m16n8k16.row.col.f32.f16.f16.f32 "
                 "{%0,%1,%2,%3}, {%4,%5,%6,%7}, {%8,%9}, {%0,%1,%2,%3};"
                 : "+f"(c[0]), "+f"(c[1]), "+f"(c[2]), "+f"(c[3])
                 : "r"(a[0]), "r"(a[1]), "r"(a[2]), "r"(a[3]), "r"(b0), "r"(b1));
}

// ---------------- preprocessing: 64x64 transpose tiles, fp16 out, 128B stores --
__global__ void tr_gu(const float* __restrict__ GU, const float* __restrict__ GUS,
                      __half* __restrict__ O) {
    __shared__ float t[64][65];
    const int tid = threadIdx.x;
    const int c0 = blockIdx.x * 64, r0 = blockIdx.y * 64, e = blockIdx.z; // c0: j, r0: h
    const float s = GUS[e * 192 + (r0 >> 7) * 12 + (c0 >> 7)];
    const float* src = GU + ((size_t)e * H_ + r0) * TWOI + c0;
    const int lr = tid >> 4, lq = tid & 15;
#pragma unroll
    for (int i = 0; i < 4; i++) {
        float4 v = *reinterpret_cast<const float4*>(src + (size_t)(lr + 16 * i) * TWOI + lq * 4);
        t[lr + 16 * i][lq * 4 + 0] = v.x; t[lr + 16 * i][lq * 4 + 1] = v.y;
        t[lr + 16 * i][lq * 4 + 2] = v.z; t[lr + 16 * i][lq * 4 + 3] = v.w;
    }
    __syncthreads();
    const int w = tid >> 5, l = tid & 31;
#pragma unroll
    for (int it = 0; it < 8; it++) {
        const int jj = w + 8 * it;
        __half2 v = __floats2half2_rn(t[2 * l][jj] * s, t[2 * l + 1][jj] * s);
        __half2* dst = reinterpret_cast<__half2*>(
            O + ((size_t)e * TWOI + c0 + jj) * H_ + r0);
        dst[l] = v;
    }
}
__global__ void tr_dn(const float* __restrict__ DN, const float* __restrict__ DNS,
                      __half* __restrict__ O) {
    __shared__ float t[64][65];
    const int tid = threadIdx.x;
    const int c0 = blockIdx.x * 64, r0 = blockIdx.y * 64;  // c0: h, r0: ei
    const float s = DNS[(r0 / I_) * 96 + ((r0 % I_) >> 7) * 16 + (c0 >> 7)];
    const float* src = DN + (size_t)r0 * H_ + c0;
    const int lr = tid >> 4, lq = tid & 15;
#pragma unroll
    for (int i = 0; i < 4; i++) {
        float4 v = *reinterpret_cast<const float4*>(src + (size_t)(lr + 16 * i) * H_ + lq * 4);
        t[lr + 16 * i][lq * 4 + 0] = v.x; t[lr + 16 * i][lq * 4 + 1] = v.y;
        t[lr + 16 * i][lq * 4 + 2] = v.z; t[lr + 16 * i][lq * 4 + 3] = v.w;
    }
    __syncthreads();
    const int w = tid >> 5, l = tid & 31;
#pragma unroll
    for (int it = 0; it < 8; it++) {
        const int jj = w + 8 * it;   // h index within tile
        __half2 v = __floats2half2_rn(t[2 * l][jj] * s, t[2 * l + 1][jj] * s);
        __half2* dst = reinterpret_cast<__half2*>(O + (size_t)(c0 + jj) * K2DIM + r0);
        dst[l] = v;
    }
}
__global__ void cv_x(const float* __restrict__ X, __half* __restrict__ O) {
    const size_t i = (size_t)blockIdx.x * 256 + threadIdx.x;
    float4 v = reinterpret_cast<const float4*>(X)[i];
    __half2* dst = reinterpret_cast<__half2*>(O) + i * 2;
    dst[0] = __floats2half2_rn(v.x, v.y);
    dst[1] = __floats2half2_rn(v.z, v.w);
}
// OUT += p1 + p2 + p3 (fixed order -> deterministic)
__global__ void addk(float* __restrict__ OUT) {
    const size_t i = (size_t)blockIdx.x * 256 + threadIdx.x;
    float4 a = reinterpret_cast<float4*>(OUT)[i];
    const float4 b = reinterpret_cast<const float4*>(g_part[0])[i];
    const float4 c = reinterpret_cast<const float4*>(g_part[1])[i];
    const float4 d = reinterpret_cast<const float4*>(g_part[2])[i];
    a.x += b.x + c.x + d.x;
    a.y += b.y + c.y + d.y;
    a.z += b.z + c.z + d.z;
    a.w += b.w + c.w + d.w;
    reinterpret_cast<float4*>(OUT)[i] = a;
}

// ---------------- main GEMM: CTA 128x128, 4 warps (2m x 2n), 64x64 warp tiles, fp16
// MODE 1: inter = rw*up*silu(gate); A=g_xt, B=g_gut rows interleaved gate/up
// MODE 2: split-K over blockIdx.z (K range z*3072..+3072); z=0 -> OUT, else g_part[z-1]
template<int MODE>
__global__ void __launch_bounds__(128, 3)
moe_mma(const float* __restrict__ RW, float* __restrict__ OUT)
{
    extern __shared__ char smraw[];
    const uint32_t sbase = (uint32_t)__cvta_generic_to_shared(smraw);
    const uint32_t sA = sbase, sB = sbase + STAGES * A_STAGE;

    const int tid = threadIdx.x, lane = tid & 31, wid = tid >> 5;
    const int warp_m = wid & 1, warp_n = wid >> 1;   // 2 x 2
    const int m0 = blockIdx.x * 128;

    int e = 0, j0 = 0, n0 = 0, koff = 0;
    const __half *Ap, *Bp;
    int lda, ldb, NC;
    float* dst2 = OUT;
    if (MODE == 1) {
        e = blockIdx.y / 12; j0 = (blockIdx.y % 12) * 64;
        Ap = g_xt; lda = H_; Bp = g_gut; ldb = H_; NC = H_ / KC;
    } else {
        n0 = blockIdx.y * 128;
        Ap = g_inter; lda = K2DIM; Bp = g_dnt; ldb = K2DIM;
        NC = K2DIM / KC / KSPLIT;                       // 48
        const int z = blockIdx.z;
        koff = z * NC * KC;                             // halves
        if (z > 0) dst2 = g_part[z - 1];
    }

    // ---- producers: quad q8 (16B = 8 halves) per thread, rows r0r + 16*i
    const int q8 = tid & 7, r0r = tid >> 3;          // r0r 0..15
    const uint32_t prow = (uint32_t)r0r * 128u + (uint32_t)((q8 ^ (r0r & 7)) << 4);
    const __half* aptr = Ap + (size_t)(m0 + r0r) * lda + q8 * 8 + koff;
    const __half* bptr;
    int bstep;
    if (MODE == 1) {
        const int sub = (r0r >> 3) & 1, o = r0r & 7;   // gate/up interleave by 8-row groups
        bptr = Bp + (size_t)((size_t)e * TWOI + sub * I_ + j0 + o) * ldb + q8 * 8;
        bstep = 8;
    } else {
        bptr = Bp + (size_t)(n0 + r0r) * ldb + q8 * 8 + koff;
        bstep = 16;
    }

    // ---- ldmatrix lane constants (fragment rows all satisfy row&7 == qq)
    const int mat = lane >> 3, qq = lane & 7;
    const int rA = (mat & 1) * 8 + qq, aSeg = mat >> 1;
    const int rB = (mat >> 1) * 8 + qq, bSeg = mat & 1;
    uint32_t xa[4], xb[4];
#pragma unroll
    for (int s = 0; s < 4; s++) {
        xa[s] = (uint32_t)(((2 * s + aSeg) ^ qq) << 4);
        xb[s] = (uint32_t)(((2 * s + bSeg) ^ qq) << 4);
    }

    float acc[4][8][4];
#pragma unroll
    for (int a = 0; a < 4; a++)
#pragma unroll
        for (int b = 0; b < 8; b++)
#pragma unroll
            for (int c = 0; c < 4; c++) acc[a][b][c] = 0.f;

    auto ISSUE = [&](int c, int slot) {
        const int k0 = c * KC;
        const uint32_t ab = sA + slot * A_STAGE + prow;
        const uint32_t bb = sB + slot * B_STAGE + prow;
#pragma unroll
        for (int i = 0; i < 8; i++) {
            cp16(ab + i * 2048u, aptr + (size_t)(16 * i) * lda + k0);
            cp16(bb + i * 2048u, bptr + (size_t)(bstep * i) * ldb + k0);
        }
        asm volatile("cp.async.commit_group;" ::: "memory");
    };
    auto COMPUTE = [&](int slot) {
        const uint32_t ab = sA + slot * A_STAGE, bb = sB + slot * B_STAGE;
        uint32_t aRow[4], bRow[4];
#pragma unroll
        for (int mi = 0; mi < 4; mi++) aRow[mi] = ab + (uint32_t)(warp_m * 64 + mi * 16 + rA) * 128u;
#pragma unroll
        for (int np = 0; np < 4; np++) bRow[np] = bb + (uint32_t)(warp_n * 64 + np * 16 + rB) * 128u;
#pragma unroll
        for (int s = 0; s < 4; s++) {
            uint32_t bf[4][4];
#pragma unroll
            for (int np = 0; np < 4; np++) ldsm4(bf[np], bRow[np] + xb[s]);
#pragma unroll
            for (int mi = 0; mi < 4; mi++) {
                uint32_t af[4];
                ldsm4(af, aRow[mi] + xa[s]);
#pragma unroll
                for (int nt = 0; nt < 8; nt++)
                    mma16816(acc[mi][nt], af, bf[nt >> 1][(nt & 1) * 2], bf[nt >> 1][(nt & 1) * 2 + 1]);
            }
        }
    };

    ISSUE(0, 0); ISSUE(1, 1);
#pragma unroll 1
    for (int c = 0; c < NC; c++) {
        asm volatile("cp.async.wait_group 1;" ::: "memory");
        __syncthreads();
        COMPUTE(c & 1);
        __syncthreads();
        if (c + 2 < NC) ISSUE(c + 2, c & 1);
    }

    // ---- epilogue
    const int g = lane >> 2, tg = lane & 3;
    if (MODE == 1) {
#pragma unroll
        for (int mi = 0; mi < 4; mi++) {
            const int r0 = m0 + warp_m * 64 + mi * 16 + g, r1 = r0 + 8;
            const float rw0 = RW[r0 * E_ + e], rw1 = RW[r1 * E_ + e];
#pragma unroll
            for (int p = 0; p < 4; p++) {
                const float* gv = acc[mi][2 * p];       // gate: even 8-row groups
                const float* uv = acc[mi][2 * p + 1];   // up: odd
                const size_t col = (size_t)e * I_ + j0 + warp_n * 32 + p * 8 + tg * 2;
                float x0 = rw0 * uv[0] * gv[0] / (1.f + __expf(-gv[0]));
                float x1 = rw0 * uv[1] * gv[1] / (1.f + __expf(-gv[1]));
                *reinterpret_cast<__half2*>(g_inter + (size_t)r0 * K2DIM + col) = __floats2half2_rn(x0, x1);
                x0 = rw1 * uv[2] * gv[2] / (1.f + __expf(-gv[2]));
                x1 = rw1 * uv[3] * gv[3] / (1.f + __expf(-gv[3]));
                *reinterpret_cast<__half2*>(g_inter + (size_t)r1 * K2DIM + col) = __floats2half2_rn(x0, x1);
            }
        }
    } else {
#pragma unroll
        for (int mi = 0; mi < 4; mi++) {
            const int r0 = m0 + warp_m * 64 + mi * 16 + g, r1 = r0 + 8;
#pragma unroll
            for (int nt = 0; nt < 8; nt++) {
                const size_t col = (size_t)n0 + warp_n * 64 + nt * 8 + tg * 2;
                float2 v;
                v.x = acc[mi][nt][0]; v.y = acc[mi][nt][1];
                *reinterpret_cast<float2*>(dst2 + (size_t)r0 * H_ + col) = v;
                v.x = acc[mi][nt][2]; v.y = acc[mi][nt][3];
                *reinterpret_cast<float2*>(dst2 + (size_t)r1 * H_ + col) = v;
            }
        }
    }
}

extern "C" void kernel_launch(void* const* d_in, const int* in_sizes, int n_in,
                              void* d_out, int out_size) {
    (void)in_sizes; (void)n_in; (void)out_size;
    const float* X   = (const float*)d_in[0];
    const float* RW  = (const float*)d_in[1];
    const float* GU  = (const float*)d_in[2];
    const float* GUS = (const float*)d_in[3];
    const float* DN  = (const float*)d_in[4];
    const float* DNS = (const float*)d_in[5];
    float* OUT = (float*)d_out;

    __half *p_gut, *p_dnt, *p_xt;
    cudaGetSymbolAddress((void**)&p_gut, g_gut);
    cudaGetSymbolAddress((void**)&p_dnt, g_dnt);
    cudaGetSymbolAddress((void**)&p_xt,  g_xt);

    tr_gu<<<dim3(TWOI / 64, H_ / 64, E_), 256>>>(GU, GUS, p_gut);
    tr_dn<<<dim3(H_ / 64, K2DIM / 64), 256>>>(DN, DNS, p_dnt);
    cv_x<<<(int)((size_t)T_ * H_ / 1024), 256>>>(X, p_xt);

    cudaFuncSetAttribute(moe_mma<1>, cudaFuncAttributeMaxDynamicSharedMemorySize, SMEM_BYTES);
    cudaFuncSetAttribute(moe_mma<2>, cudaFuncAttributeMaxDynamicSharedMemorySize, SMEM_BYTES);

    moe_mma<1><<<dim3(32, 192), 128, SMEM_BYTES>>>(RW, nullptr);
    moe_mma<2><<<dim3(32, 16, KSPLIT), 128, SMEM_BYTES>>>(nullptr, OUT);
    addk<<<(int)((size_t)T_ * H_ / 1024), 256>>>(OUT);
}

// round 14
// speedup vs baseline: 4.1261x; 1.0182x over previous
#include <cuda_runtime.h>
#include <cuda_fp16.h>
#include <stdint.h>
#include <math.h>

#define E_ 16
#define H_ 2048
#define I_ 768
#define TWOI 1536
#define T_ 4096
#define K2DIM 12288
#define KC 64
#define KSPLIT 4

#define A_STAGE (128*128)   // 128 rows x 64 halves (128B)
#define B_STAGE (128*128)

__device__ __half g_inter[(size_t)T_ * K2DIM];    // [T][E*I]
__device__ __half g_gut [(size_t)E_ * TWOI * H_]; // [e][j'][h] scaled (j'<768 gate else up)
__device__ __half g_dnt [(size_t)H_ * K2DIM];     // [h][e*I+i] scaled
__device__ __half g_xt  [(size_t)T_ * H_];        // fp16(X)
__device__ float  g_part[KSPLIT - 1][(size_t)T_ * H_]; // split-K partials (z=1..3)

static __device__ __forceinline__ void ldsm4(uint32_t r[4], uint32_t a) {
    asm volatile("ldmatrix.sync.aligned.m8n8.x4.shared.b16 {%0,%1,%2,%3}, [%4];"
                 : "=r"(r[0]), "=r"(r[1]), "=r"(r[2]), "=r"(r[3]) : "r"(a));
}
static __device__ __forceinline__ void cp16(uint32_t d, const void* s) {
    asm volatile("cp.async.cg.shared.global [%0], [%1], 16;" :: "r"(d), "l"(s) : "memory");
}
static __device__ __forceinline__ void mma16816(float c[4], const uint32_t a[4], uint32_t b0, uint32_t b1) {
    asm volatile("mma.sync.aligned.m16n8k16.row.col.f32.f16.f16.f32 "
                 "{%0,%1,%2,%3}, {%4,%5,%6,%7}, {%8,%9}, {%0,%1,%2,%3};"
                 : "+f"(c[0]), "+f"(c[1]), "+f"(c[2]), "+f"(c[3])
                 : "r"(a[0]), "r"(a[1]), "r"(a[2]), "r"(a[3]), "r"(b0), "r"(b1));
}

// ---------------- preprocessing: 64x64 transpose tiles, fp16 out, 128B stores --
__global__ void tr_gu(const float* __restrict__ GU, const float* __restrict__ GUS,
                      __half* __restrict__ O) {
    __shared__ float t[64][65];
    const int tid = threadIdx.x;
    const int c0 = blockIdx.x * 64, r0 = blockIdx.y * 64, e = blockIdx.z; // c0: j, r0: h
    const float s = GUS[e * 192 + (r0 >> 7) * 12 + (c0 >> 7)];
    const float* src = GU + ((size_t)e * H_ + r0) * TWOI + c0;
    const int lr = tid >> 4, lq = tid & 15;
#pragma unroll
    for (int i = 0; i < 4; i++) {
        float4 v = *reinterpret_cast<const float4*>(src + (size_t)(lr + 16 * i) * TWOI + lq * 4);
        t[lr + 16 * i][lq * 4 + 0] = v.x; t[lr + 16 * i][lq * 4 + 1] = v.y;
        t[lr + 16 * i][lq * 4 + 2] = v.z; t[lr + 16 * i][lq * 4 + 3] = v.w;
    }
    __syncthreads();
    const int w = tid >> 5, l = tid & 31;
#pragma unroll
    for (int it = 0; it < 8; it++) {
        const int jj = w + 8 * it;
        __half2 v = __floats2half2_rn(t[2 * l][jj] * s, t[2 * l + 1][jj] * s);
        __half2* dst = reinterpret_cast<__half2*>(
            O + ((size_t)e * TWOI + c0 + jj) * H_ + r0);
        dst[l] = v;
    }
}
__global__ void tr_dn(const float* __restrict__ DN, const float* __restrict__ DNS,
                      __half* __restrict__ O) {
    __shared__ float t[64][65];
    const int tid = threadIdx.x;
    const int c0 = blockIdx.x * 64, r0 = blockIdx.y * 64;  // c0: h, r0: ei
    const float s = DNS[(r0 / I_) * 96 + ((r0 % I_) >> 7) * 16 + (c0 >> 7)];
    const float* src = DN + (size_t)r0 * H_ + c0;
    const int lr = tid >> 4, lq = tid & 15;
#pragma unroll
    for (int i = 0; i < 4; i++) {
        float4 v = *reinterpret_cast<const float4*>(src + (size_t)(lr + 16 * i) * H_ + lq * 4);
        t[lr + 16 * i][lq * 4 + 0] = v.x; t[lr + 16 * i][lq * 4 + 1] = v.y;
        t[lr + 16 * i][lq * 4 + 2] = v.z; t[lr + 16 * i][lq * 4 + 3] = v.w;
    }
    __syncthreads();
    const int w = tid >> 5, l = tid & 31;
#pragma unroll
    for (int it = 0; it < 8; it++) {
        const int jj = w + 8 * it;   // h index within tile
        __half2 v = __floats2half2_rn(t[2 * l][jj] * s, t[2 * l + 1][jj] * s);
        __half2* dst = reinterpret_cast<__half2*>(O + (size_t)(c0 + jj) * K2DIM + r0);
        dst[l] = v;
    }
}
__global__ void cv_x(const float* __restrict__ X, __half* __restrict__ O) {
    const size_t i = (size_t)blockIdx.x * 256 + threadIdx.x;
    float4 v = reinterpret_cast<const float4*>(X)[i];
    __half2* dst = reinterpret_cast<__half2*>(O) + i * 2;
    dst[0] = __floats2half2_rn(v.x, v.y);
    dst[1] = __floats2half2_rn(v.z, v.w);
}
// OUT += p1 + p2 + p3 (fixed order -> deterministic)
__global__ void addk(float* __restrict__ OUT) {
    const size_t i = (size_t)blockIdx.x * 256 + threadIdx.x;
    float4 a = reinterpret_cast<float4*>(OUT)[i];
    const float4 b = reinterpret_cast<const float4*>(g_part[0])[i];
    const float4 c = reinterpret_cast<const float4*>(g_part[1])[i];
    const float4 d = reinterpret_cast<const float4*>(g_part[2])[i];
    a.x += b.x + c.x + d.x;
    a.y += b.y + c.y + d.y;
    a.z += b.z + c.z + d.z;
    a.w += b.w + c.w + d.w;
    reinterpret_cast<float4*>(OUT)[i] = a;
}

// ---------------- main GEMM: CTA 128x128, 4 warps (2m x 2n), 64x64 warp tiles, fp16
// MODE 1: 3-stage, single sync/chunk, cp.async interleaved into compute (2 CTAs/SM)
// MODE 2: 2-stage, two syncs/chunk (3 CTAs/SM) — proven round-13 path, split-K z
template<int MODE>
__global__ void __launch_bounds__(128, (MODE == 1) ? 2 : 3)
moe_mma(const float* __restrict__ RW, float* __restrict__ OUT)
{
    constexpr int NST = (MODE == 1) ? 3 : 2;
    extern __shared__ char smraw[];
    const uint32_t sbase = (uint32_t)__cvta_generic_to_shared(smraw);
    const uint32_t sA = sbase, sB = sbase + NST * A_STAGE;

    const int tid = threadIdx.x, lane = tid & 31, wid = tid >> 5;
    const int warp_m = wid & 1, warp_n = wid >> 1;   // 2 x 2
    const int m0 = blockIdx.x * 128;

    int e = 0, j0 = 0, n0 = 0, koff = 0;
    const __half *Ap, *Bp;
    int lda, ldb, NC;
    float* dst2 = OUT;
    if (MODE == 1) {
        e = blockIdx.y / 12; j0 = (blockIdx.y % 12) * 64;
        Ap = g_xt; lda = H_; Bp = g_gut; ldb = H_; NC = H_ / KC;
    } else {
        n0 = blockIdx.y * 128;
        Ap = g_inter; lda = K2DIM; Bp = g_dnt; ldb = K2DIM;
        NC = K2DIM / KC / KSPLIT;                       // 48
        const int z = blockIdx.z;
        koff = z * NC * KC;                             // halves
        if (z > 0) dst2 = g_part[z - 1];
    }

    // ---- producers: quad q8 (16B = 8 halves) per thread, rows r0r + 16*i
    const int q8 = tid & 7, r0r = tid >> 3;          // r0r 0..15
    const uint32_t prow = (uint32_t)r0r * 128u + (uint32_t)((q8 ^ (r0r & 7)) << 4);
    const __half* aptr = Ap + (size_t)(m0 + r0r) * lda + q8 * 8 + koff;
    const __half* bptr;
    int bstep;
    if (MODE == 1) {
        const int sub = (r0r >> 3) & 1, o = r0r & 7;   // gate/up interleave by 8-row groups
        bptr = Bp + (size_t)((size_t)e * TWOI + sub * I_ + j0 + o) * ldb + q8 * 8;
        bstep = 8;
    } else {
        bptr = Bp + (size_t)(n0 + r0r) * ldb + q8 * 8 + koff;
        bstep = 16;
    }

    // ---- ldmatrix lane constants (fragment rows all satisfy row&7 == qq)
    const int mat = lane >> 3, qq = lane & 7;
    const int rA = (mat & 1) * 8 + qq, aSeg = mat >> 1;
    const int rB = (mat >> 1) * 8 + qq, bSeg = mat & 1;
    uint32_t xa[4], xb[4];
#pragma unroll
    for (int s = 0; s < 4; s++) {
        xa[s] = (uint32_t)(((2 * s + aSeg) ^ qq) << 4);
        xb[s] = (uint32_t)(((2 * s + bSeg) ^ qq) << 4);
    }

    float acc[4][8][4];
#pragma unroll
    for (int a = 0; a < 4; a++)
#pragma unroll
        for (int b = 0; b < 8; b++)
#pragma unroll
            for (int c = 0; c < 4; c++) acc[a][b][c] = 0.f;

    auto ISSUE = [&](int c, int slot) {
        const int k0 = c * KC;
        const uint32_t ab = sA + slot * A_STAGE + prow;
        const uint32_t bb = sB + slot * B_STAGE + prow;
#pragma unroll
        for (int i = 0; i < 8; i++) {
            cp16(ab + i * 2048u, aptr + (size_t)(16 * i) * lda + k0);
            cp16(bb + i * 2048u, bptr + (size_t)(bstep * i) * ldb + k0);
        }
        asm volatile("cp.async.commit_group;" ::: "memory");
    };

    if (MODE == 1) {
        // ---- 3-stage, single sync, interleaved producer
        ISSUE(0, 0); ISSUE(1, 1);
#pragma unroll 1
        for (int c = 0; c < NC; c++) {
            asm volatile("cp.async.wait_group 1;" ::: "memory");
            __syncthreads();
            const int rs = c % 3;
            const int ws = (c + 2) % 3;
            const bool w = (c + 2) < NC;
            const int k0n = (c + 2) * KC;
            const uint32_t abw = sA + ws * A_STAGE + prow;
            const uint32_t bbw = sB + ws * B_STAGE + prow;
            const uint32_t ab = sA + rs * A_STAGE, bb = sB + rs * B_STAGE;
            uint32_t aRow[4], bRow[4];
#pragma unroll
            for (int mi = 0; mi < 4; mi++) aRow[mi] = ab + (uint32_t)(warp_m * 64 + mi * 16 + rA) * 128u;
#pragma unroll
            for (int np = 0; np < 4; np++) bRow[np] = bb + (uint32_t)(warp_n * 64 + np * 16 + rB) * 128u;
#pragma unroll
            for (int s = 0; s < 4; s++) {
                if (w) {
                    cp16(abw + (uint32_t)(2 * s) * 2048u,     aptr + (size_t)(16 * (2 * s)) * lda + k0n);
                    cp16(abw + (uint32_t)(2 * s + 1) * 2048u, aptr + (size_t)(16 * (2 * s + 1)) * lda + k0n);
                    cp16(bbw + (uint32_t)(2 * s) * 2048u,     bptr + (size_t)(bstep * (2 * s)) * ldb + k0n);
                    cp16(bbw + (uint32_t)(2 * s + 1) * 2048u, bptr + (size_t)(bstep * (2 * s + 1)) * ldb + k0n);
                }
                uint32_t bf[4][4];
#pragma unroll
                for (int np = 0; np < 4; np++) ldsm4(bf[np], bRow[np] + xb[s]);
#pragma unroll
                for (int mi = 0; mi < 4; mi++) {
                    uint32_t af[4];
                    ldsm4(af, aRow[mi] + xa[s]);
#pragma unroll
                    for (int nt = 0; nt < 8; nt++)
                        mma16816(acc[mi][nt], af, bf[nt >> 1][(nt & 1) * 2], bf[nt >> 1][(nt & 1) * 2 + 1]);
                }
            }
            asm volatile("cp.async.commit_group;" ::: "memory");
        }
    } else {
        // ---- proven 2-stage path (round 13)
        ISSUE(0, 0); ISSUE(1, 1);
#pragma unroll 1
        for (int c = 0; c < NC; c++) {
            asm volatile("cp.async.wait_group 1;" ::: "memory");
            __syncthreads();
            const int slot = c & 1;
            const uint32_t ab = sA + slot * A_STAGE, bb = sB + slot * B_STAGE;
            uint32_t aRow[4], bRow[4];
#pragma unroll
            for (int mi = 0; mi < 4; mi++) aRow[mi] = ab + (uint32_t)(warp_m * 64 + mi * 16 + rA) * 128u;
#pragma unroll
            for (int np = 0; np < 4; np++) bRow[np] = bb + (uint32_t)(warp_n * 64 + np * 16 + rB) * 128u;
#pragma unroll
            for (int s = 0; s < 4; s++) {
                uint32_t bf[4][4];
#pragma unroll
                for (int np = 0; np < 4; np++) ldsm4(bf[np], bRow[np] + xb[s]);
#pragma unroll
                for (int mi = 0; mi < 4; mi++) {
                    uint32_t af[4];
                    ldsm4(af, aRow[mi] + xa[s]);
#pragma unroll
                    for (int nt = 0; nt < 8; nt++)
                        mma16816(acc[mi][nt], af, bf[nt >> 1][(nt & 1) * 2], bf[nt >> 1][(nt & 1) * 2 + 1]);
                }
            }
            __syncthreads();
            if (c + 2 < NC) ISSUE(c + 2, slot);
        }
    }

    // ---- epilogue
    const int g = lane >> 2, tg = lane & 3;
    if (MODE == 1) {
#pragma unroll
        for (int mi = 0; mi < 4; mi++) {
            const int r0 = m0 + warp_m * 64 + mi * 16 + g, r1 = r0 + 8;
            const float rw0 = RW[r0 * E_ + e], rw1 = RW[r1 * E_ + e];
#pragma unroll
            for (int p = 0; p < 4; p++) {
                const float* gv = acc[mi][2 * p];       // gate: even 8-row groups
                const float* uv = acc[mi][2 * p + 1];   // up: odd
                const size_t col = (size_t)e * I_ + j0 + warp_n * 32 + p * 8 + tg * 2;
                float x0 = rw0 * uv[0] * gv[0] / (1.f + __expf(-gv[0]));
                float x1 = rw0 * uv[1] * gv[1] / (1.f + __expf(-gv[1]));
                *reinterpret_cast<__half2*>(g_inter + (size_t)r0 * K2DIM + col) = __floats2half2_rn(x0, x1);
                x0 = rw1 * uv[2] * gv[2] / (1.f + __expf(-gv[2]));
                x1 = rw1 * uv[3] * gv[3] / (1.f + __expf(-gv[3]));
                *reinterpret_cast<__half2*>(g_inter + (size_t)r1 * K2DIM + col) = __floats2half2_rn(x0, x1);
            }
        }
    } else {
#pragma unroll
        for (int mi = 0; mi < 4; mi++) {
            const int r0 = m0 + warp_m * 64 + mi * 16 + g, r1 = r0 + 8;
#pragma unroll
            for (int nt = 0; nt < 8; nt++) {
                const size_t col = (size_t)n0 + warp_n * 64 + nt * 8 + tg * 2;
                float2 v;
                v.x = acc[mi][nt][0]; v.y = acc[mi][nt][1];
                *reinterpret_cast<float2*>(dst2 + (size_t)r0 * H_ + col) = v;
                v.x = acc[mi][nt][2]; v.y = acc[mi][nt][3];
                *reinterpret_cast<float2*>(dst2 + (size_t)r1 * H_ + col) = v;
            }
        }
    }
}

extern "C" void kernel_launch(void* const* d_in, const int* in_sizes, int n_in,
                              void* d_out, int out_size) {
    (void)in_sizes; (void)n_in; (void)out_size;
    const float* X   = (const float*)d_in[0];
    const float* RW  = (const float*)d_in[1];
    const float* GU  = (const float*)d_in[2];
    const float* GUS = (const float*)d_in[3];
    const float* DN  = (const float*)d_in[4];
    const float* DNS = (const float*)d_in[5];
    float* OUT = (float*)d_out;

    __half *p_gut, *p_dnt, *p_xt;
    cudaGetSymbolAddress((void**)&p_gut, g_gut);
    cudaGetSymbolAddress((void**)&p_dnt, g_dnt);
    cudaGetSymbolAddress((void**)&p_xt,  g_xt);

    tr_gu<<<dim3(TWOI / 64, H_ / 64, E_), 256>>>(GU, GUS, p_gut);
    tr_dn<<<dim3(H_ / 64, K2DIM / 64), 256>>>(DN, DNS, p_dnt);
    cv_x<<<(int)((size_t)T_ * H_ / 1024), 256>>>(X, p_xt);

    const int SM1 = 3 * (A_STAGE + B_STAGE);   // 96KB
    const int SM2 = 2 * (A_STAGE + B_STAGE);   // 64KB
    cudaFuncSetAttribute(moe_mma<1>, cudaFuncAttributeMaxDynamicSharedMemorySize, SM1);
    cudaFuncSetAttribute(moe_mma<2>, cudaFuncAttributeMaxDynamicSharedMemorySize, SM2);

    moe_mma<1><<<dim3(32, 192), 128, SM1>>>(RW, nullptr);
    moe_mma<2><<<dim3(32, 16, KSPLIT), 128, SM2>>>(nullptr, OUT);
    addk<<<(int)((size_t)T_ * H_ / 1024), 256>>>(OUT);
}

// round 15
// speedup vs baseline: 4.1512x; 1.0061x over previous
#include <cuda_runtime.h>
#include <cuda_fp16.h>
#include <stdint.h>
#include <math.h>

#define E_ 16
#define H_ 2048
#define I_ 768
#define TWOI 1536
#define T_ 4096
#define K2DIM 12288
#define KC 64
#define KSPLIT 4

#define A_STAGE (128*128)   // 128 rows x 64 halves (128B)
#define B_STAGE (128*128)

__device__ __half g_inter[(size_t)T_ * K2DIM];    // [T][E*I]
__device__ __half g_gut [(size_t)E_ * TWOI * H_]; // [e][j'][h] scaled (j'<768 gate else up)
__device__ __half g_dnt [(size_t)H_ * K2DIM];     // [h][e*I+i] scaled
__device__ __half g_xt  [(size_t)T_ * H_];        // fp16(X)
__device__ float  g_part[KSPLIT - 1][(size_t)T_ * H_]; // split-K partials (z=1..3)

static __device__ __forceinline__ void ldsm4(uint32_t r[4], uint32_t a) {
    asm volatile("ldmatrix.sync.aligned.m8n8.x4.shared.b16 {%0,%1,%2,%3}, [%4];"
                 : "=r"(r[0]), "=r"(r[1]), "=r"(r[2]), "=r"(r[3]) : "r"(a));
}
static __device__ __forceinline__ void cp16(uint32_t d, const void* s) {
    asm volatile("cp.async.cg.shared.global [%0], [%1], 16;" :: "r"(d), "l"(s) : "memory");
}
static __device__ __forceinline__ void mma16816(float c[4], const uint32_t a[4], uint32_t b0, uint32_t b1) {
    asm volatile("mma.sync.aligned.m16n8k16.row.col.f32.f16.f16.f32 "
                 "{%0,%1,%2,%3}, {%4,%5,%6,%7}, {%8,%9}, {%0,%1,%2,%3};"
                 : "+f"(c[0]), "+f"(c[1]), "+f"(c[2]), "+f"(c[3])
                 : "r"(a[0]), "r"(a[1]), "r"(a[2]), "r"(a[3]), "r"(b0), "r"(b1));
}

// ---------------- preprocessing: 64x64 transpose tiles, fp16 out, 128B stores --
__global__ void tr_gu(const float* __restrict__ GU, const float* __restrict__ GUS,
                      __half* __restrict__ O) {
    __shared__ float t[64][65];
    const int tid = threadIdx.x;
    const int c0 = blockIdx.x * 64, r0 = blockIdx.y * 64, e = blockIdx.z; // c0: j, r0: h
    const float s = GUS[e * 192 + (r0 >> 7) * 12 + (c0 >> 7)];
    const float* src = GU + ((size_t)e * H_ + r0) * TWOI + c0;
    const int lr = tid >> 4, lq = tid & 15;
#pragma unroll
    for (int i = 0; i < 4; i++) {
        float4 v = *reinterpret_cast<const float4*>(src + (size_t)(lr + 16 * i) * TWOI + lq * 4);
        t[lr + 16 * i][lq * 4 + 0] = v.x; t[lr + 16 * i][lq * 4 + 1] = v.y;
        t[lr + 16 * i][lq * 4 + 2] = v.z; t[lr + 16 * i][lq * 4 + 3] = v.w;
    }
    __syncthreads();
    const int w = tid >> 5, l = tid & 31;
#pragma unroll
    for (int it = 0; it < 8; it++) {
        const int jj = w + 8 * it;
        __half2 v = __floats2half2_rn(t[2 * l][jj] * s, t[2 * l + 1][jj] * s);
        __half2* dst = reinterpret_cast<__half2*>(
            O + ((size_t)e * TWOI + c0 + jj) * H_ + r0);
        dst[l] = v;
    }
}
__global__ void tr_dn(const float* __restrict__ DN, const float* __restrict__ DNS,
                      __half* __restrict__ O) {
    __shared__ float t[64][65];
    const int tid = threadIdx.x;
    const int c0 = blockIdx.x * 64, r0 = blockIdx.y * 64;  // c0: h, r0: ei
    const float s = DNS[(r0 / I_) * 96 + ((r0 % I_) >> 7) * 16 + (c0 >> 7)];
    const float* src = DN + (size_t)r0 * H_ + c0;
    const int lr = tid >> 4, lq = tid & 15;
#pragma unroll
    for (int i = 0; i < 4; i++) {
        float4 v = *reinterpret_cast<const float4*>(src + (size_t)(lr + 16 * i) * H_ + lq * 4);
        t[lr + 16 * i][lq * 4 + 0] = v.x; t[lr + 16 * i][lq * 4 + 1] = v.y;
        t[lr + 16 * i][lq * 4 + 2] = v.z; t[lr + 16 * i][lq * 4 + 3] = v.w;
    }
    __syncthreads();
    const int w = tid >> 5, l = tid & 31;
#pragma unroll
    for (int it = 0; it < 8; it++) {
        const int jj = w + 8 * it;   // h index within tile
        __half2 v = __floats2half2_rn(t[2 * l][jj] * s, t[2 * l + 1][jj] * s);
        __half2* dst = reinterpret_cast<__half2*>(O + (size_t)(c0 + jj) * K2DIM + r0);
        dst[l] = v;
    }
}
__global__ void cv_x(const float* __restrict__ X, __half* __restrict__ O) {
    const size_t i = (size_t)blockIdx.x * 256 + threadIdx.x;
    float4 v = reinterpret_cast<const float4*>(X)[i];
    __half2* dst = reinterpret_cast<__half2*>(O) + i * 2;
    dst[0] = __floats2half2_rn(v.x, v.y);
    dst[1] = __floats2half2_rn(v.z, v.w);
}
// OUT += p1 + p2 + p3 (fixed order -> deterministic)
__global__ void addk(float* __restrict__ OUT) {
    const size_t i = (size_t)blockIdx.x * 256 + threadIdx.x;
    float4 a = reinterpret_cast<float4*>(OUT)[i];
    const float4 b = reinterpret_cast<const float4*>(g_part[0])[i];
    const float4 c = reinterpret_cast<const float4*>(g_part[1])[i];
    const float4 d = reinterpret_cast<const float4*>(g_part[2])[i];
    a.x += b.x + c.x + d.x;
    a.y += b.y + c.y + d.y;
    a.z += b.z + c.z + d.z;
    a.w += b.w + c.w + d.w;
    reinterpret_cast<float4*>(OUT)[i] = a;
}

// ---------------- main GEMM: CTA 128x128, 4 warps (2m x 2n), 64x64 warp tiles, fp16
// Both modes: 3-stage, single sync/chunk, cp.async interleaved into compute, 2 CTAs/SM
// MODE 1: inter = rw*up*silu(gate); A=g_xt, B=g_gut rows interleaved gate/up
// MODE 2: split-K over blockIdx.z (K range z*3072..+3072); z=0 -> OUT, else g_part[z-1]
template<int MODE>
__global__ void __launch_bounds__(128, 2)
moe_mma(const float* __restrict__ RW, float* __restrict__ OUT)
{
    extern __shared__ char smraw[];
    const uint32_t sbase = (uint32_t)__cvta_generic_to_shared(smraw);
    const uint32_t sA = sbase, sB = sbase + 3 * A_STAGE;

    const int tid = threadIdx.x, lane = tid & 31, wid = tid >> 5;
    const int warp_m = wid & 1, warp_n = wid >> 1;   // 2 x 2
    const int m0 = blockIdx.x * 128;

    int e = 0, j0 = 0, n0 = 0, koff = 0;
    const __half *Ap, *Bp;
    int lda, ldb, NC;
    float* dst2 = OUT;
    if (MODE == 1) {
        e = blockIdx.y / 12; j0 = (blockIdx.y % 12) * 64;
        Ap = g_xt; lda = H_; Bp = g_gut; ldb = H_; NC = H_ / KC;
    } else {
        n0 = blockIdx.y * 128;
        Ap = g_inter; lda = K2DIM; Bp = g_dnt; ldb = K2DIM;
        NC = K2DIM / KC / KSPLIT;                       // 48
        const int z = blockIdx.z;
        koff = z * NC * KC;                             // halves
        if (z > 0) dst2 = g_part[z - 1];
    }

    // ---- producers: quad q8 (16B = 8 halves) per thread, rows r0r + 16*i
    const int q8 = tid & 7, r0r = tid >> 3;          // r0r 0..15
    const uint32_t prow = (uint32_t)r0r * 128u + (uint32_t)((q8 ^ (r0r & 7)) << 4);
    const __half* aptr = Ap + (size_t)(m0 + r0r) * lda + q8 * 8 + koff;
    const __half* bptr;
    int bstep;
    if (MODE == 1) {
        const int sub = (r0r >> 3) & 1, o = r0r & 7;   // gate/up interleave by 8-row groups
        bptr = Bp + (size_t)((size_t)e * TWOI + sub * I_ + j0 + o) * ldb + q8 * 8;
        bstep = 8;
    } else {
        bptr = Bp + (size_t)(n0 + r0r) * ldb + q8 * 8 + koff;
        bstep = 16;
    }

    // ---- ldmatrix lane constants (fragment rows all satisfy row&7 == qq)
    const int mat = lane >> 3, qq = lane & 7;
    const int rA = (mat & 1) * 8 + qq, aSeg = mat >> 1;
    const int rB = (mat >> 1) * 8 + qq, bSeg = mat & 1;
    uint32_t xa[4], xb[4];
#pragma unroll
    for (int s = 0; s < 4; s++) {
        xa[s] = (uint32_t)(((2 * s + aSeg) ^ qq) << 4);
        xb[s] = (uint32_t)(((2 * s + bSeg) ^ qq) << 4);
    }

    float acc[4][8][4];
#pragma unroll
    for (int a = 0; a < 4; a++)
#pragma unroll
        for (int b = 0; b < 8; b++)
#pragma unroll
            for (int c = 0; c < 4; c++) acc[a][b][c] = 0.f;

    auto ISSUE = [&](int c, int slot) {
        const int k0 = c * KC;
        const uint32_t ab = sA + slot * A_STAGE + prow;
        const uint32_t bb = sB + slot * B_STAGE + prow;
#pragma unroll
        for (int i = 0; i < 8; i++) {
            cp16(ab + i * 2048u, aptr + (size_t)(16 * i) * lda + k0);
            cp16(bb + i * 2048u, bptr + (size_t)(bstep * i) * ldb + k0);
        }
        asm volatile("cp.async.commit_group;" ::: "memory");
    };

    // ---- 3-stage, single sync, interleaved producer (both modes)
    ISSUE(0, 0); ISSUE(1, 1);
#pragma unroll 1
    for (int c = 0; c < NC; c++) {
        asm volatile("cp.async.wait_group 1;" ::: "memory");
        __syncthreads();
        const int rs = c % 3;
        const int ws = (c + 2) % 3;
        const bool w = (c + 2) < NC;
        const int k0n = (c + 2) * KC;
        const uint32_t abw = sA + ws * A_STAGE + prow;
        const uint32_t bbw = sB + ws * B_STAGE + prow;
        const uint32_t ab = sA + rs * A_STAGE, bb = sB + rs * B_STAGE;
        uint32_t aRow[4], bRow[4];
#pragma unroll
        for (int mi = 0; mi < 4; mi++) aRow[mi] = ab + (uint32_t)(warp_m * 64 + mi * 16 + rA) * 128u;
#pragma unroll
        for (int np = 0; np < 4; np++) bRow[np] = bb + (uint32_t)(warp_n * 64 + np * 16 + rB) * 128u;
#pragma unroll
        for (int s = 0; s < 4; s++) {
            if (w) {
                cp16(abw + (uint32_t)(2 * s) * 2048u,     aptr + (size_t)(16 * (2 * s)) * lda + k0n);
                cp16(abw + (uint32_t)(2 * s + 1) * 2048u, aptr + (size_t)(16 * (2 * s + 1)) * lda + k0n);
                cp16(bbw + (uint32_t)(2 * s) * 2048u,     bptr + (size_t)(bstep * (2 * s)) * ldb + k0n);
                cp16(bbw + (uint32_t)(2 * s + 1) * 2048u, bptr + (size_t)(bstep * (2 * s + 1)) * ldb + k0n);
            }
            uint32_t bf[4][4];
#pragma unroll
            for (int np = 0; np < 4; np++) ldsm4(bf[np], bRow[np] + xb[s]);
#pragma unroll
            for (int mi = 0; mi < 4; mi++) {
                uint32_t af[4];
                ldsm4(af, aRow[mi] + xa[s]);
#pragma unroll
                for (int nt = 0; nt < 8; nt++)
                    mma16816(acc[mi][nt], af, bf[nt >> 1][(nt & 1) * 2], bf[nt >> 1][(nt & 1) * 2 + 1]);
            }
        }
        asm volatile("cp.async.commit_group;" ::: "memory");
    }

    // ---- epilogue
    const int g = lane >> 2, tg = lane & 3;
    if (MODE == 1) {
#pragma unroll
        for (int mi = 0; mi < 4; mi++) {
            const int r0 = m0 + warp_m * 64 + mi * 16 + g, r1 = r0 + 8;
            const float rw0 = RW[r0 * E_ + e], rw1 = RW[r1 * E_ + e];
#pragma unroll
            for (int p = 0; p < 4; p++) {
                const float* gv = acc[mi][2 * p];       // gate: even 8-row groups
                const float* uv = acc[mi][2 * p + 1];   // up: odd
                const size_t col = (size_t)e * I_ + j0 + warp_n * 32 + p * 8 + tg * 2;
                float x0 = rw0 * uv[0] * gv[0] / (1.f + __expf(-gv[0]));
                float x1 = rw0 * uv[1] * gv[1] / (1.f + __expf(-gv[1]));
                *reinterpret_cast<__half2*>(g_inter + (size_t)r0 * K2DIM + col) = __floats2half2_rn(x0, x1);
                x0 = rw1 * uv[2] * gv[2] / (1.f + __expf(-gv[2]));
                x1 = rw1 * uv[3] * gv[3] / (1.f + __expf(-gv[3]));
                *reinterpret_cast<__half2*>(g_inter + (size_t)r1 * K2DIM + col) = __floats2half2_rn(x0, x1);
            }
        }
    } else {
#pragma unroll
        for (int mi = 0; mi < 4; mi++) {
            const int r0 = m0 + warp_m * 64 + mi * 16 + g, r1 = r0 + 8;
#pragma unroll
            for (int nt = 0; nt < 8; nt++) {
                const size_t col = (size_t)n0 + warp_n * 64 + nt * 8 + tg * 2;
                float2 v;
                v.x = acc[mi][nt][0]; v.y = acc[mi][nt][1];
                *reinterpret_cast<float2*>(dst2 + (size_t)r0 * H_ + col) = v;
                v.x = acc[mi][nt][2]; v.y = acc[mi][nt][3];
                *reinterpret_cast<float2*>(dst2 + (size_t)r1 * H_ + col) = v;
            }
        }
    }
}

extern "C" void kernel_launch(void* const* d_in, const int* in_sizes, int n_in,
                              void* d_out, int out_size) {
    (void)in_sizes; (void)n_in; (void)out_size;
    const float* X   = (const float*)d_in[0];
    const float* RW  = (const float*)d_in[1];
    const float* GU  = (const float*)d_in[2];
    const float* GUS = (const float*)d_in[3];
    const float* DN  = (const float*)d_in[4];
    const float* DNS = (const float*)d_in[5];
    float* OUT = (float*)d_out;

    __half *p_gut, *p_dnt, *p_xt;
    cudaGetSymbolAddress((void**)&p_gut, g_gut);
    cudaGetSymbolAddress((void**)&p_dnt, g_dnt);
    cudaGetSymbolAddress((void**)&p_xt,  g_xt);

    tr_gu<<<dim3(TWOI / 64, H_ / 64, E_), 256>>>(GU, GUS, p_gut);
    tr_dn<<<dim3(H_ / 64, K2DIM / 64), 256>>>(DN, DNS, p_dnt);
    cv_x<<<(int)((size_t)T_ * H_ / 1024), 256>>>(X, p_xt);

    const int SM3 = 3 * (A_STAGE + B_STAGE);   // 96KB -> 2 CTAs/SM
    cudaFuncSetAttribute(moe_mma<1>, cudaFuncAttributeMaxDynamicSharedMemorySize, SM3);
    cudaFuncSetAttribute(moe_mma<2>, cudaFuncAttributeMaxDynamicSharedMemorySize, SM3);

    moe_mma<1><<<dim3(32, 192), 128, SM3>>>(RW, nullptr);
    moe_mma<2><<<dim3(32, 16, KSPLIT), 128, SM3>>>(nullptr, OUT);
    addk<<<(int)((size_t)T_ * H_ / 1024), 256>>>(OUT);
}

// round 16
// speedup vs baseline: 4.3018x; 1.0363x over previous
#include <cuda_runtime.h>
#include <cuda_fp16.h>
#include <stdint.h>
#include <math.h>

#define E_ 16
#define H_ 2048
#define I_ 768
#define TWOI 1536
#define T_ 4096
#define K2DIM 12288
#define KC 64
#define KSPLIT 4

#define A_STAGE (128*128)   // 128 rows x 64 halves (128B)
#define B_STAGE (128*128)

__device__ __half g_inter[(size_t)T_ * K2DIM];    // [T][E*I]
__device__ __half g_gut [(size_t)E_ * TWOI * H_]; // [e][j'][h] scaled (j'<768 gate else up)
__device__ __half g_dnt [(size_t)H_ * K2DIM];     // [h][e*I+i] scaled
__device__ __half g_xt  [(size_t)T_ * H_];        // fp16(X)
__device__ float  g_part[KSPLIT - 1][(size_t)T_ * H_]; // split-K partials (z=1..3)

static __device__ __forceinline__ void ldsm4(uint32_t r[4], uint32_t a) {
    asm volatile("ldmatrix.sync.aligned.m8n8.x4.shared.b16 {%0,%1,%2,%3}, [%4];"
                 : "=r"(r[0]), "=r"(r[1]), "=r"(r[2]), "=r"(r[3]) : "r"(a));
}
static __device__ __forceinline__ void cp16(uint32_t d, const void* s) {
    asm volatile("cp.async.cg.shared.global [%0], [%1], 16;" :: "r"(d), "l"(s) : "memory");
}
static __device__ __forceinline__ void mma16816(float c[4], const uint32_t a[4], uint32_t b0, uint32_t b1) {
    asm volatile("mma.sync.aligned.m16n8k16.row.col.f32.f16.f16.f32 "
                 "{%0,%1,%2,%3}, {%4,%5,%6,%7}, {%8,%9}, {%0,%1,%2,%3};"
                 : "+f"(c[0]), "+f"(c[1]), "+f"(c[2]), "+f"(c[3])
                 : "r"(a[0]), "r"(a[1]), "r"(a[2]), "r"(a[3]), "r"(b0), "r"(b1));
}

// ---------------- preprocessing: 64x64 transpose tiles, fp16 out, 128B stores --
__global__ void tr_gu(const float* __restrict__ GU, const float* __restrict__ GUS,
                      __half* __restrict__ O) {
    __shared__ float t[64][65];
    const int tid = threadIdx.x;
    const int c0 = blockIdx.x * 64, r0 = blockIdx.y * 64, e = blockIdx.z; // c0: j, r0: h
    const float s = GUS[e * 192 + (r0 >> 7) * 12 + (c0 >> 7)];
    const float* src = GU + ((size_t)e * H_ + r0) * TWOI + c0;
    const int lr = tid >> 4, lq = tid & 15;
#pragma unroll
    for (int i = 0; i < 4; i++) {
        float4 v = *reinterpret_cast<const float4*>(src + (size_t)(lr + 16 * i) * TWOI + lq * 4);
        t[lr + 16 * i][lq * 4 + 0] = v.x; t[lr + 16 * i][lq * 4 + 1] = v.y;
        t[lr + 16 * i][lq * 4 + 2] = v.z; t[lr + 16 * i][lq * 4 + 3] = v.w;
    }
    __syncthreads();
    const int w = tid >> 5, l = tid & 31;
#pragma unroll
    for (int it = 0; it < 8; it++) {
        const int jj = w + 8 * it;
        __half2 v = __floats2half2_rn(t[2 * l][jj] * s, t[2 * l + 1][jj] * s);
        __half2* dst = reinterpret_cast<__half2*>(
            O + ((size_t)e * TWOI + c0 + jj) * H_ + r0);
        dst[l] = v;
    }
}
__global__ void tr_dn(const float* __restrict__ DN, const float* __restrict__ DNS,
                      __half* __restrict__ O) {
    __shared__ float t[64][65];
    const int tid = threadIdx.x;
    const int c0 = blockIdx.x * 64, r0 = blockIdx.y * 64;  // c0: h, r0: ei
    const float s = DNS[(r0 / I_) * 96 + ((r0 % I_) >> 7) * 16 + (c0 >> 7)];
    const float* src = DN + (size_t)r0 * H_ + c0;
    const int lr = tid >> 4, lq = tid & 15;
#pragma unroll
    for (int i = 0; i < 4; i++) {
        float4 v = *reinterpret_cast<const float4*>(src + (size_t)(lr + 16 * i) * H_ + lq * 4);
        t[lr + 16 * i][lq * 4 + 0] = v.x; t[lr + 16 * i][lq * 4 + 1] = v.y;
        t[lr + 16 * i][lq * 4 + 2] = v.z; t[lr + 16 * i][lq * 4 + 3] = v.w;
    }
    __syncthreads();
    const int w = tid >> 5, l = tid & 31;
#pragma unroll
    for (int it = 0; it < 8; it++) {
        const int jj = w + 8 * it;   // h index within tile
        __half2 v = __floats2half2_rn(t[2 * l][jj] * s, t[2 * l + 1][jj] * s);
        __half2* dst = reinterpret_cast<__half2*>(O + (size_t)(c0 + jj) * K2DIM + r0);
        dst[l] = v;
    }
}
__global__ void cv_x(const float* __restrict__ X, __half* __restrict__ O) {
    const size_t i = (size_t)blockIdx.x * 256 + threadIdx.x;
    float4 v = reinterpret_cast<const float4*>(X)[i];
    __half2* dst = reinterpret_cast<__half2*>(O) + i * 2;
    dst[0] = __floats2half2_rn(v.x, v.y);
    dst[1] = __floats2half2_rn(v.z, v.w);
}
// OUT += p1 + p2 + p3 (fixed order -> deterministic)
__global__ void addk(float* __restrict__ OUT) {
    const size_t i = (size_t)blockIdx.x * 256 + threadIdx.x;
    float4 a = reinterpret_cast<float4*>(OUT)[i];
    const float4 b = reinterpret_cast<const float4*>(g_part[0])[i];
    const float4 c = reinterpret_cast<const float4*>(g_part[1])[i];
    const float4 d = reinterpret_cast<const float4*>(g_part[2])[i];
    a.x += b.x + c.x + d.x;
    a.y += b.y + c.y + d.y;
    a.z += b.z + c.z + d.z;
    a.w += b.w + c.w + d.w;
    reinterpret_cast<float4*>(OUT)[i] = a;
}

// ---------------- main GEMM: CTA 128x128, 4 warps (2m x 2n), 64x64 warp tiles, fp16
// Both modes: 3-stage, single sync/chunk, interleaved producer, and software-
// pipelined fragment double-buffering (prefetch s+1 LDSM during s MMAs).
// MODE 1: inter = rw*up*silu(gate); A=g_xt, B=g_gut rows interleaved gate/up
// MODE 2: split-K over blockIdx.z (K range z*3072..+3072); z=0 -> OUT, else g_part[z-1]
template<int MODE>
__global__ void __launch_bounds__(128, 2)
moe_mma(const float* __restrict__ RW, float* __restrict__ OUT)
{
    extern __shared__ char smraw[];
    const uint32_t sbase = (uint32_t)__cvta_generic_to_shared(smraw);
    const uint32_t sA = sbase, sB = sbase + 3 * A_STAGE;

    const int tid = threadIdx.x, lane = tid & 31, wid = tid >> 5;
    const int warp_m = wid & 1, warp_n = wid >> 1;   // 2 x 2
    const int m0 = blockIdx.x * 128;

    int e = 0, j0 = 0, n0 = 0, koff = 0;
    const __half *Ap, *Bp;
    int lda, ldb, NC;
    float* dst2 = OUT;
    if (MODE == 1) {
        e = blockIdx.y / 12; j0 = (blockIdx.y % 12) * 64;
        Ap = g_xt; lda = H_; Bp = g_gut; ldb = H_; NC = H_ / KC;
    } else {
        n0 = blockIdx.y * 128;
        Ap = g_inter; lda = K2DIM; Bp = g_dnt; ldb = K2DIM;
        NC = K2DIM / KC / KSPLIT;                       // 48
        const int z = blockIdx.z;
        koff = z * NC * KC;                             // halves
        if (z > 0) dst2 = g_part[z - 1];
    }

    // ---- producers: quad q8 (16B = 8 halves) per thread, rows r0r + 16*i
    const int q8 = tid & 7, r0r = tid >> 3;          // r0r 0..15
    const uint32_t prow = (uint32_t)r0r * 128u + (uint32_t)((q8 ^ (r0r & 7)) << 4);
    const __half* aptr = Ap + (size_t)(m0 + r0r) * lda + q8 * 8 + koff;
    const __half* bptr;
    int bstep;
    if (MODE == 1) {
        const int sub = (r0r >> 3) & 1, o = r0r & 7;   // gate/up interleave by 8-row groups
        bptr = Bp + (size_t)((size_t)e * TWOI + sub * I_ + j0 + o) * ldb + q8 * 8;
        bstep = 8;
    } else {
        bptr = Bp + (size_t)(n0 + r0r) * ldb + q8 * 8 + koff;
        bstep = 16;
    }

    // ---- ldmatrix lane constants (fragment rows all satisfy row&7 == qq)
    const int mat = lane >> 3, qq = lane & 7;
    const int rA = (mat & 1) * 8 + qq, aSeg = mat >> 1;
    const int rB = (mat >> 1) * 8 + qq, bSeg = mat & 1;
    uint32_t xa[4], xb[4];
#pragma unroll
    for (int s = 0; s < 4; s++) {
        xa[s] = (uint32_t)(((2 * s + aSeg) ^ qq) << 4);
        xb[s] = (uint32_t)(((2 * s + bSeg) ^ qq) << 4);
    }

    float acc[4][8][4];
#pragma unroll
    for (int a = 0; a < 4; a++)
#pragma unroll
        for (int b = 0; b < 8; b++)
#pragma unroll
            for (int c = 0; c < 4; c++) acc[a][b][c] = 0.f;

    auto ISSUE = [&](int c, int slot) {
        const int k0 = c * KC;
        const uint32_t ab = sA + slot * A_STAGE + prow;
        const uint32_t bb = sB + slot * B_STAGE + prow;
#pragma unroll
        for (int i = 0; i < 8; i++) {
            cp16(ab + i * 2048u, aptr + (size_t)(16 * i) * lda + k0);
            cp16(bb + i * 2048u, bptr + (size_t)(bstep * i) * ldb + k0);
        }
        asm volatile("cp.async.commit_group;" ::: "memory");
    };

    // ---- 3-stage, single sync, interleaved producer + fragment double-buffer
    ISSUE(0, 0); ISSUE(1, 1);
#pragma unroll 1
    for (int c = 0; c < NC; c++) {
        asm volatile("cp.async.wait_group 1;" ::: "memory");
        __syncthreads();
        const int rs = c % 3;
        const int ws = (c + 2) % 3;
        const bool w = (c + 2) < NC;
        const int k0n = (c + 2) * KC;
        const uint32_t abw = sA + ws * A_STAGE + prow;
        const uint32_t bbw = sB + ws * B_STAGE + prow;
        const uint32_t ab = sA + rs * A_STAGE, bb = sB + rs * B_STAGE;
        uint32_t aRow[4], bRow[4];
#pragma unroll
        for (int mi = 0; mi < 4; mi++) aRow[mi] = ab + (uint32_t)(warp_m * 64 + mi * 16 + rA) * 128u;
#pragma unroll
        for (int np = 0; np < 4; np++) bRow[np] = bb + (uint32_t)(warp_n * 64 + np * 16 + rB) * 128u;

        uint32_t af[2][4][4], bf[2][4][4];
        // preload fragments for s = 0
#pragma unroll
        for (int np = 0; np < 4; np++) ldsm4(bf[0][np], bRow[np] + xb[0]);
#pragma unroll
        for (int mi = 0; mi < 4; mi++) ldsm4(af[0][mi], aRow[mi] + xa[0]);

#pragma unroll
        for (int s = 0; s < 4; s++) {
            const int cur = s & 1, nx = cur ^ 1;
            if (s < 3) {   // prefetch next s-step fragments while MMAs drain
#pragma unroll
                for (int np = 0; np < 4; np++) ldsm4(bf[nx][np], bRow[np] + xb[s + 1]);
#pragma unroll
                for (int mi = 0; mi < 4; mi++) ldsm4(af[nx][mi], aRow[mi] + xa[s + 1]);
            }
            if (w) {       // interleaved producer: 4 cp.async per s-step
                cp16(abw + (uint32_t)(2 * s) * 2048u,     aptr + (size_t)(16 * (2 * s)) * lda + k0n);
                cp16(abw + (uint32_t)(2 * s + 1) * 2048u, aptr + (size_t)(16 * (2 * s + 1)) * lda + k0n);
                cp16(bbw + (uint32_t)(2 * s) * 2048u,     bptr + (size_t)(bstep * (2 * s)) * ldb + k0n);
                cp16(bbw + (uint32_t)(2 * s + 1) * 2048u, bptr + (size_t)(bstep * (2 * s + 1)) * ldb + k0n);
            }
#pragma unroll
            for (int mi = 0; mi < 4; mi++)
#pragma unroll
                for (int nt = 0; nt < 8; nt++)
                    mma16816(acc[mi][nt], af[cur][mi],
                             bf[cur][nt >> 1][(nt & 1) * 2], bf[cur][nt >> 1][(nt & 1) * 2 + 1]);
        }
        asm volatile("cp.async.commit_group;" ::: "memory");
    }

    // ---- epilogue
    const int g = lane >> 2, tg = lane & 3;
    if (MODE == 1) {
#pragma unroll
        for (int mi = 0; mi < 4; mi++) {
            const int r0 = m0 + warp_m * 64 + mi * 16 + g, r1 = r0 + 8;
            const float rw0 = RW[r0 * E_ + e], rw1 = RW[r1 * E_ + e];
#pragma unroll
            for (int p = 0; p < 4; p++) {
                const float* gv = acc[mi][2 * p];       // gate: even 8-row groups
                const float* uv = acc[mi][2 * p + 1];   // up: odd
                const size_t col = (size_t)e * I_ + j0 + warp_n * 32 + p * 8 + tg * 2;
                float x0 = rw0 * uv[0] * gv[0] / (1.f + __expf(-gv[0]));
                float x1 = rw0 * uv[1] * gv[1] / (1.f + __expf(-gv[1]));
                *reinterpret_cast<__half2*>(g_inter + (size_t)r0 * K2DIM + col) = __floats2half2_rn(x0, x1);
                x0 = rw1 * uv[2] * gv[2] / (1.f + __expf(-gv[2]));
                x1 = rw1 * uv[3] * gv[3] / (1.f + __expf(-gv[3]));
                *reinterpret_cast<__half2*>(g_inter + (size_t)r1 * K2DIM + col) = __floats2half2_rn(x0, x1);
            }
        }
    } else {
#pragma unroll
        for (int mi = 0; mi < 4; mi++) {
            const int r0 = m0 + warp_m * 64 + mi * 16 + g, r1 = r0 + 8;
#pragma unroll
            for (int nt = 0; nt < 8; nt++) {
                const size_t col = (size_t)n0 + warp_n * 64 + nt * 8 + tg * 2;
                float2 v;
                v.x = acc[mi][nt][0]; v.y = acc[mi][nt][1];
                *reinterpret_cast<float2*>(dst2 + (size_t)r0 * H_ + col) = v;
                v.x = acc[mi][nt][2]; v.y = acc[mi][nt][3];
                *reinterpret_cast<float2*>(dst2 + (size_t)r1 * H_ + col) = v;
            }
        }
    }
}

extern "C" void kernel_launch(void* const* d_in, const int* in_sizes, int n_in,
                              void* d_out, int out_size) {
    (void)in_sizes; (void)n_in; (void)out_size;
    const float* X   = (const float*)d_in[0];
    const float* RW  = (const float*)d_in[1];
    const float* GU  = (const float*)d_in[2];
    const float* GUS = (const float*)d_in[3];
    const float* DN  = (const float*)d_in[4];
    const float* DNS = (const float*)d_in[5];
    float* OUT = (float*)d_out;

    __half *p_gut, *p_dnt, *p_xt;
    cudaGetSymbolAddress((void**)&p_gut, g_gut);
    cudaGetSymbolAddress((void**)&p_dnt, g_dnt);
    cudaGetSymbolAddress((void**)&p_xt,  g_xt);

    tr_gu<<<dim3(TWOI / 64, H_ / 64, E_), 256>>>(GU, GUS, p_gut);
    tr_dn<<<dim3(H_ / 64, K2DIM / 64), 256>>>(DN, DNS, p_dnt);
    cv_x<<<(int)((size_t)T_ * H_ / 1024), 256>>>(X, p_xt);

    const int SM3 = 3 * (A_STAGE + B_STAGE);   // 96KB -> 2 CTAs/SM
    cudaFuncSetAttribute(moe_mma<1>, cudaFuncAttributeMaxDynamicSharedMemorySize, SM3);
    cudaFuncSetAttribute(moe_mma<2>, cudaFuncAttributeMaxDynamicSharedMemorySize, SM3);

    moe_mma<1><<<dim3(32, 192), 128, SM3>>>(RW, nullptr);
    moe_mma<2><<<dim3(32, 16, KSPLIT), 128, SM3>>>(nullptr, OUT);
    addk<<<(int)((size_t)T_ * H_ / 1024), 256>>>(OUT);
}